// round 1
// baseline (speedup 1.0000x reference)
#include <cuda_runtime.h>
#include <math.h>
#include <stdint.h>

// ---------------- problem constants ----------------
#define W     8192      // words
#define LC    16        // chars per word (padded)
#define CD    100       // char emb dim
#define CDP   112       // padded to %8 for GEMM
#define WD    300       // word emb dim
#define HD    512       // hidden dim (bi)
#define HH    256       // per-direction hidden
#define G4    1024      // 4*HH gates
#define WDIN  812       // WD + HD
#define WDINP 816       // padded
#define T1    48
#define T2    32

#define ALN __align__(16)

// ---------------- static device scratch (no cudaMalloc allowed) ----------------
__device__ ALN float g_Xc[(size_t)LC * W * CDP];     // gathered char embeddings, padded
__device__ ALN float g_XG[(size_t)LC * W * G4];      // char input gates (one direction at a time)
__device__ ALN float g_G[(size_t)W * G4];            // per-step gate scratch
__device__ ALN float g_Hf[(size_t)W * HH];
__device__ ALN float g_Hb[(size_t)W * HH];
__device__ ALN float g_Cc[(size_t)W * HH];
__device__ ALN float g_WX[(size_t)W * WDINP];        // word-lstm input, padded
__device__ ALN float g_XGw[(size_t)2 * W * G4];      // word input gates (both dirs)
__device__ ALN float g_OUT[(size_t)W * HD];          // word BiLSTM outputs
__device__ ALN float g_WihC[2][G4 * CDP];            // packed char Wih (padded)
__device__ ALN float g_WihW[2][G4 * WDINP];          // packed word Wih (padded)
__device__ ALN float g_bias[4][G4];                  // bih+bhh for cf, cb, wf, wb
__device__ volatile float g_hex[2][2][HH];           // word-lstm h exchange, double-buffered
__device__ volatile unsigned g_ctr[2];               // word-lstm barrier counters

__device__ __forceinline__ float sigmoidf_(float x) { return 1.0f / (1.0f + expf(-x)); }

// ---------------- small utility kernels ----------------
__global__ void zero_kernel(float* p, size_t n) {
    size_t i = (size_t)blockIdx.x * blockDim.x + threadIdx.x;
    if (i < n) p[i] = 0.0f;
}

__global__ void zero_ctr_kernel() {
    if (threadIdx.x < 2) g_ctr[threadIdx.x] = 0u;
}

// pack [1024 x 100] -> [1024 x 112] zero-padded
__global__ void pack_wihc_kernel(const float* __restrict__ src, float* __restrict__ dst) {
    int n = blockIdx.x;
    for (int k = threadIdx.x; k < CDP; k += blockDim.x)
        dst[n * CDP + k] = (k < CD) ? src[n * CD + k] : 0.0f;
}

// pack [1024 x 812] -> [1024 x 816] zero-padded
__global__ void pack_wihw_kernel(const float* __restrict__ src, float* __restrict__ dst) {
    int n = blockIdx.x;
    for (int k = threadIdx.x; k < WDINP; k += blockDim.x)
        dst[n * WDINP + k] = (k < WDIN) ? src[n * WDIN + k] : 0.0f;
}

__global__ void bias_sum_kernel(const float* __restrict__ a, const float* __restrict__ b,
                                float* __restrict__ o) {
    int i = blockIdx.x * blockDim.x + threadIdx.x;
    if (i < G4) o[i] = a[i] + b[i];
}

// gather char embeddings: Xc[(t*W + w)][k] = char_emb[cseq[w*LC + t]][k], zero pad
__global__ void gather_char_kernel(const int* __restrict__ cseq, const float* __restrict__ cemb,
                                   float* __restrict__ Xc) {
    int id = blockIdx.x;            // 0 .. LC*W-1, id = t*W + w
    int t = id >> 13;               // /8192
    int w = id & (W - 1);
    int ci = cseq[w * LC + t];
    float* dst = Xc + (size_t)id * CDP;
    const float* src = cemb + (size_t)ci * CD;
    for (int k = threadIdx.x; k < CDP; k += blockDim.x)
        dst[k] = (k < CD) ? src[k] : 0.0f;
}

// gather word lstm input: WX[w] = [word_emb[wseq[w]] (300) | Hf[w] (256) | Hb[w] (256) | pad]
__global__ void gather_word_kernel(const int* __restrict__ wseq, const float* __restrict__ wemb,
                                   const float* __restrict__ Hf, const float* __restrict__ Hb,
                                   float* __restrict__ WX) {
    int w = blockIdx.x;
    int wi = wseq[w];
    float* dst = WX + (size_t)w * WDINP;
    for (int k = threadIdx.x; k < WDINP; k += blockDim.x) {
        float v;
        if (k < WD)            v = wemb[(size_t)wi * WD + k];
        else if (k < WD + HH)  v = Hf[(size_t)w * HH + (k - WD)];
        else if (k < WDIN)     v = Hb[(size_t)w * HH + (k - WD - HH)];
        else                   v = 0.0f;
        dst[k] = v;
    }
}

// ---------------- tiled SGEMM: C[M,N] = A[M,K] @ B[N,K]^T (+ bias[N]) (+ D[M,N]) ----------------
// requires M%128==0, N%128==0, K%8==0, all rows 16B aligned.
__global__ __launch_bounds__(256, 2) void sgemm_kernel(
    const float* __restrict__ A, const float* __restrict__ B,
    const float* __restrict__ bias, const float* __restrict__ D,
    float* __restrict__ C, int N, int K)
{
    __shared__ ALN float As[8][128];
    __shared__ ALN float Bs[8][128];

    int tid = threadIdx.x;
    int bx = blockIdx.x, by = blockIdx.y;
    int tx = tid & 15, ty = tid >> 4;

    const float* Ab = A + (size_t)(by * 128) * K;
    const float* Bb = B + (size_t)(bx * 128) * K;
    int lrow = tid >> 1;
    int lcol = (tid & 1) * 4;

    float acc[8][8];
#pragma unroll
    for (int i = 0; i < 8; i++)
#pragma unroll
        for (int j = 0; j < 8; j++) acc[i][j] = 0.0f;

    float4 a4 = *(const float4*)(Ab + (size_t)lrow * K + lcol);
    float4 b4 = *(const float4*)(Bb + (size_t)lrow * K + lcol);

    for (int k0 = 0; k0 < K; k0 += 8) {
        __syncthreads();
        As[lcol + 0][lrow] = a4.x; As[lcol + 1][lrow] = a4.y;
        As[lcol + 2][lrow] = a4.z; As[lcol + 3][lrow] = a4.w;
        Bs[lcol + 0][lrow] = b4.x; Bs[lcol + 1][lrow] = b4.y;
        Bs[lcol + 2][lrow] = b4.z; Bs[lcol + 3][lrow] = b4.w;
        __syncthreads();

        if (k0 + 8 < K) {   // software pipeline: prefetch next tile
            a4 = *(const float4*)(Ab + (size_t)lrow * K + (k0 + 8) + lcol);
            b4 = *(const float4*)(Bb + (size_t)lrow * K + (k0 + 8) + lcol);
        }

#pragma unroll
        for (int kk = 0; kk < 8; kk++) {
            float4 av0 = *(const float4*)&As[kk][ty * 8];
            float4 av1 = *(const float4*)&As[kk][ty * 8 + 4];
            float4 bv0 = *(const float4*)&Bs[kk][tx * 8];
            float4 bv1 = *(const float4*)&Bs[kk][tx * 8 + 4];
            float av[8] = {av0.x, av0.y, av0.z, av0.w, av1.x, av1.y, av1.z, av1.w};
            float bv[8] = {bv0.x, bv0.y, bv0.z, bv0.w, bv1.x, bv1.y, bv1.z, bv1.w};
#pragma unroll
            for (int i = 0; i < 8; i++)
#pragma unroll
                for (int j = 0; j < 8; j++)
                    acc[i][j] = fmaf(av[i], bv[j], acc[i][j]);
        }
    }

    int row0 = by * 128 + ty * 8;
    int col0 = bx * 128 + tx * 8;
#pragma unroll
    for (int i = 0; i < 8; i++) {
        size_t rbase = (size_t)(row0 + i) * N;
#pragma unroll
        for (int j = 0; j < 8; j += 4) {
            int col = col0 + j;
            float4 v = make_float4(acc[i][j], acc[i][j + 1], acc[i][j + 2], acc[i][j + 3]);
            if (bias) {
                float4 bb = *(const float4*)&bias[col];
                v.x += bb.x; v.y += bb.y; v.z += bb.z; v.w += bb.w;
            }
            if (D) {
                float4 dd = *(const float4*)&D[rbase + col];
                v.x += dd.x; v.y += dd.y; v.z += dd.z; v.w += dd.w;
            }
            *(float4*)&C[rbase + col] = v;
        }
    }
}

// ---------------- char LSTM pointwise update (masked) ----------------
__global__ void char_update_kernel(const float* __restrict__ Gm, const int* __restrict__ lens,
                                   float* __restrict__ Hs, float* __restrict__ Cs, int t)
{
    int idx = blockIdx.x * blockDim.x + threadIdx.x;   // w*256 + j
    int w = idx >> 8;
    int j = idx & 255;
    if (t >= lens[w]) return;   // masked: keep h, c
    const float* gr = Gm + (size_t)w * G4;
    float gi = gr[j], gf = gr[256 + j], gg = gr[512 + j], go = gr[768 + j];
    float c = Cs[idx];
    float cn = sigmoidf_(gf) * c + sigmoidf_(gi) * tanhf(gg);
    float hn = sigmoidf_(go) * tanhf(cn);
    Hs[idx] = hn;
    Cs[idx] = cn;
}

// ---------------- sequential word BiLSTM: persistent kernel, 16 co-resident CTAs ----------------
// blockIdx: d = bid/8 (0=fwd, 1=bwd), b = bid%8 (cells [b*32, b*32+32)).
// 256 threads: tid = half*128 + r; r = g*32 + jj. Thread owns Whh[g*256 + b*32 + jj][half*128 .. +128)
// in registers. h exchanged via double-buffered global + atomic counter barrier.
__global__ __launch_bounds__(256, 1) void word_lstm_kernel(
    const float* __restrict__ XGw,          // [2][W][1024]
    const float* __restrict__ WhhF, const float* __restrict__ WhhB,
    float* __restrict__ OUT)                // [W][512]
{
    int bid = blockIdx.x;
    int d = bid >> 3;
    int b = bid & 7;
    int tid = threadIdx.x;
    int half = tid >> 7;
    int r = tid & 127;
    int g = r >> 5, jj = r & 31;
    int rowg = g * 256 + b * 32 + jj;

    const float* Whh = d ? WhhB : WhhF;
    const float* xgbase = XGw + (size_t)d * W * G4;

    __shared__ ALN float h_sh[HH];
    __shared__ ALN float psum[256];
    __shared__ ALN float gsh[128];

    float wreg[128];
#pragma unroll
    for (int i = 0; i < 128; i += 4) {
        float4 v = *(const float4*)(Whh + (size_t)rowg * HH + half * 128 + i);
        wreg[i] = v.x; wreg[i + 1] = v.y; wreg[i + 2] = v.z; wreg[i + 3] = v.w;
    }
    if (tid < 64) *(float4*)&h_sh[tid * 4] = make_float4(0.f, 0.f, 0.f, 0.f);
    float c = 0.0f;
    __syncthreads();

    for (int t = 0; t < W; t++) {
        int p = d ? (W - 1 - t) : t;
        float xg = __ldg(xgbase + (size_t)p * G4 + rowg);   // issued early, used after MACs

        float s0 = 0.f, s1 = 0.f, s2 = 0.f, s3 = 0.f;
#pragma unroll
        for (int i = 0; i < 128; i += 4) {
            float4 h4 = *(const float4*)&h_sh[half * 128 + i];
            s0 = fmaf(h4.x, wreg[i],     s0);
            s1 = fmaf(h4.y, wreg[i + 1], s1);
            s2 = fmaf(h4.z, wreg[i + 2], s2);
            s3 = fmaf(h4.w, wreg[i + 3], s3);
        }
        psum[tid] = (s0 + s1) + (s2 + s3);
        __syncthreads();

        if (tid < 128) gsh[tid] = xg + psum[tid] + psum[tid + 128];
        __syncthreads();

        int buf = (t + 1) & 1;
        if (tid < 32) {
            float gi = gsh[tid], gf = gsh[32 + tid], gg = gsh[64 + tid], go = gsh[96 + tid];
            float cn = sigmoidf_(gf) * c + sigmoidf_(gi) * tanhf(gg);
            c = cn;
            float hn = sigmoidf_(go) * tanhf(cn);
            g_hex[d][buf][b * 32 + tid] = hn;
            OUT[(size_t)p * HD + d * HH + b * 32 + tid] = hn;
            __threadfence();
        }
        __syncthreads();

        if (tid == 0) {
            __threadfence();   // cumulative: orders all block stores before the arrive
            atomicAdd((unsigned*)&g_ctr[d], 1u);
            unsigned target = 8u * (unsigned)(t + 1);
            while (*(volatile unsigned*)&g_ctr[d] < target) { }
            __threadfence();
        }
        __syncthreads();

        if (tid < 64) {
            int i4 = tid * 4;
            float x0 = g_hex[d][buf][i4];
            float x1 = g_hex[d][buf][i4 + 1];
            float x2 = g_hex[d][buf][i4 + 2];
            float x3 = g_hex[d][buf][i4 + 3];
            *(float4*)&h_sh[i4] = make_float4(x0, x1, x2, x3);
        }
        __syncthreads();
    }
}

// ---------------- heads: logits + log_softmax ----------------
__global__ __launch_bounds__(128) void heads_kernel(
    const float* __restrict__ OUT,
    const float* __restrict__ Wp, const float* __restrict__ bp,
    const float* __restrict__ Wp2, const float* __restrict__ bp2,
    float* __restrict__ out)
{
    int w = blockIdx.x;
    __shared__ ALN float osh[HD];
    __shared__ ALN float lsh[T1 + T2];
    int tid = threadIdx.x;
    int lane = tid & 31, wid = tid >> 5;

    for (int k = tid; k < HD; k += 128) osh[k] = OUT[(size_t)w * HD + k];
    __syncthreads();

    for (int l = wid; l < T1 + T2; l += 4) {
        const float* wr = (l < T1) ? (Wp + (size_t)l * HD) : (Wp2 + (size_t)(l - T1) * HD);
        float s = 0.0f;
#pragma unroll 4
        for (int k = lane; k < HD; k += 32) s = fmaf(osh[k], wr[k], s);
#pragma unroll
        for (int o = 16; o; o >>= 1) s += __shfl_xor_sync(0xFFFFFFFFu, s, o);
        if (lane == 0) lsh[l] = s + ((l < T1) ? bp[l] : bp2[l - T1]);
    }
    __syncthreads();

    if (wid < 2) {
        int T = (wid == 0) ? T1 : T2;
        int base = (wid == 0) ? 0 : T1;
        float* ob = (wid == 0) ? (out + (size_t)w * T1)
                               : (out + (size_t)W * T1 + (size_t)w * T2);
        float mx = -1e30f;
        for (int l = lane; l < T; l += 32) mx = fmaxf(mx, lsh[base + l]);
#pragma unroll
        for (int o = 16; o; o >>= 1) mx = fmaxf(mx, __shfl_xor_sync(0xFFFFFFFFu, mx, o));
        float se = 0.0f;
        for (int l = lane; l < T; l += 32) se += expf(lsh[base + l] - mx);
#pragma unroll
        for (int o = 16; o; o >>= 1) se += __shfl_xor_sync(0xFFFFFFFFu, se, o);
        float lz = mx + logf(se);
        for (int l = lane; l < T; l += 32) ob[l] = lsh[base + l] - lz;
    }
}

// ---------------- host orchestration ----------------
static void* sym(const void* s) {
    void* p = nullptr;
    cudaGetSymbolAddress(&p, s);
    return p;
}

extern "C" void kernel_launch(void* const* d_in, const int* in_sizes, int n_in,
                              void* d_out, int out_size)
{
    const int*   wseq  = (const int*)d_in[0];
    const int*   cseq  = (const int*)d_in[1];
    const int*   lens  = (const int*)d_in[2];
    const float* cemb  = (const float*)d_in[3];
    const float* wemb  = (const float*)d_in[4];
    const float* cfWih = (const float*)d_in[5];
    const float* cfWhh = (const float*)d_in[6];
    const float* cfbih = (const float*)d_in[7];
    const float* cfbhh = (const float*)d_in[8];
    const float* cbWih = (const float*)d_in[9];
    const float* cbWhh = (const float*)d_in[10];
    const float* cbbih = (const float*)d_in[11];
    const float* cbbhh = (const float*)d_in[12];
    const float* wfWih = (const float*)d_in[13];
    const float* wfWhh = (const float*)d_in[14];
    const float* wfbih = (const float*)d_in[15];
    const float* wfbhh = (const float*)d_in[16];
    const float* wbWih = (const float*)d_in[17];
    const float* wbWhh = (const float*)d_in[18];
    const float* wbbih = (const float*)d_in[19];
    const float* wbbhh = (const float*)d_in[20];
    const float* Wp    = (const float*)d_in[21];
    const float* bp    = (const float*)d_in[22];
    const float* Wp2   = (const float*)d_in[23];
    const float* bp2   = (const float*)d_in[24];
    float* outp = (float*)d_out;

    float* Xc   = (float*)sym(g_Xc);
    float* XG   = (float*)sym(g_XG);
    float* G    = (float*)sym(g_G);
    float* Hf   = (float*)sym(g_Hf);
    float* Hb   = (float*)sym(g_Hb);
    float* Cc   = (float*)sym(g_Cc);
    float* WX   = (float*)sym(g_WX);
    float* XGw  = (float*)sym(g_XGw);
    float* OUT  = (float*)sym(g_OUT);
    float* WihC = (float*)sym(g_WihC);
    float* WihW = (float*)sym(g_WihW);
    float* bias = (float*)sym(g_bias);

    // ---- pack weights / biases ----
    pack_wihc_kernel<<<G4, 128>>>(cfWih, WihC + 0 * (size_t)G4 * CDP);
    pack_wihc_kernel<<<G4, 128>>>(cbWih, WihC + 1 * (size_t)G4 * CDP);
    pack_wihw_kernel<<<G4, 256>>>(wfWih, WihW + 0 * (size_t)G4 * WDINP);
    pack_wihw_kernel<<<G4, 256>>>(wbWih, WihW + 1 * (size_t)G4 * WDINP);
    bias_sum_kernel<<<4, 256>>>(cfbih, cfbhh, bias + 0 * G4);
    bias_sum_kernel<<<4, 256>>>(cbbih, cbbhh, bias + 1 * G4);
    bias_sum_kernel<<<4, 256>>>(wfbih, wfbhh, bias + 2 * G4);
    bias_sum_kernel<<<4, 256>>>(wbbih, wbbhh, bias + 3 * G4);

    // ---- gather char embeddings ----
    gather_char_kernel<<<LC * W, 128>>>(cseq, cemb, Xc);

    // ---- char BiLSTM, one direction at a time (XG buffer reused) ----
    const size_t nWH = (size_t)W * HH;
    for (int dir = 0; dir < 2; dir++) {
        float* Hdir = dir ? Hb : Hf;
        const float* Whh = dir ? cbWhh : cfWhh;
        zero_kernel<<<(unsigned)((nWH + 255) / 256), 256>>>(Hdir, nWH);
        zero_kernel<<<(unsigned)((nWH + 255) / 256), 256>>>(Cc, nWH);

        // XG = Xc @ WihT + (bih+bhh):  M = LC*W = 131072, K = 112, N = 1024
        sgemm_kernel<<<dim3(G4 / 128, (LC * W) / 128), 256>>>(
            Xc, WihC + (size_t)dir * G4 * CDP, bias + (size_t)dir * G4, nullptr, XG, G4, CDP);

        for (int s = 0; s < LC; s++) {
            int t = dir ? (LC - 1 - s) : s;
            // G = H @ WhhT + XG[t]:  M = 8192, K = 256, N = 1024
            sgemm_kernel<<<dim3(G4 / 128, W / 128), 256>>>(
                Hdir, Whh, nullptr, XG + (size_t)t * W * G4, G, G4, HH);
            char_update_kernel<<<(W * HH) / 256, 256>>>(G, lens, Hdir, Cc, t);
        }
    }

    // ---- word-level input ----
    gather_word_kernel<<<W, 256>>>(wseq, wemb, Hf, Hb, WX);
    // XGw = WX @ WihT + bias:  M = 8192, K = 816, N = 1024
    sgemm_kernel<<<dim3(G4 / 128, W / 128), 256>>>(
        WX, WihW + 0 * (size_t)G4 * WDINP, bias + 2 * G4, nullptr, XGw, G4, WDINP);
    sgemm_kernel<<<dim3(G4 / 128, W / 128), 256>>>(
        WX, WihW + 1 * (size_t)G4 * WDINP, bias + 3 * G4, nullptr, XGw + (size_t)W * G4, G4, WDINP);

    // ---- sequential word BiLSTM (both directions concurrently) ----
    zero_ctr_kernel<<<1, 32>>>();
    word_lstm_kernel<<<16, 256>>>(XGw, wfWhh, wbWhh, OUT);

    // ---- heads + log_softmax ----
    heads_kernel<<<W, 128>>>(OUT, Wp, bp, Wp2, bp2, outp);

    (void)in_sizes; (void)n_in; (void)out_size;
}

// round 3
// speedup vs baseline: 1.0767x; 1.0767x over previous
#include <cuda_runtime.h>
#include <math.h>
#include <stdint.h>

// ---------------- problem constants ----------------
#define W     8192      // words
#define LC    16        // chars per word (padded)
#define CD    100       // char emb dim
#define CDP   128       // padded to %32 for tensor GEMM
#define WD    300       // word emb dim
#define HD    512       // hidden dim (bi)
#define HH    256       // per-direction hidden
#define G4    1024      // 4*HH gates
#define WDIN  812       // WD + HD
#define WDINP 832       // padded to %32
#define T1    48
#define T2    32

#define ALN __align__(16)

// smem layout constants for GEMM (floats)
#define KCH   32                 // K chunk
#define RPAD  36                 // padded row stride (conflict-free fragment reads)
#define ABUF  (128 * RPAD)       // 4608 floats per matrix tile
#define BUFSZ (2 * ABUF)         // A + B per buffer
#define GEMM_SMEM_BYTES (2 * BUFSZ * 4)   // 73728 B

// ---------------- static device scratch (no cudaMalloc allowed) ----------------
__device__ ALN float g_Xc[(size_t)LC * W * CDP];
__device__ ALN float g_XG[(size_t)LC * W * G4];
__device__ ALN float g_G[(size_t)W * G4];
__device__ ALN float g_Hf[(size_t)W * HH];
__device__ ALN float g_Hb[(size_t)W * HH];
__device__ ALN float g_Cc[(size_t)W * HH];
__device__ ALN float g_WX[(size_t)W * WDINP];
__device__ ALN float g_XGw[(size_t)2 * W * G4];
__device__ ALN float g_OUT[(size_t)W * HD];
__device__ ALN float g_WihC[2][G4 * CDP];
__device__ ALN float g_WihW[2][G4 * WDINP];
__device__ ALN float g_bias[4][G4];
__device__ volatile float g_hex[2][2][HH];
__device__ volatile unsigned g_ctr[2];

__device__ __forceinline__ float sigmoidf_(float x) { return 1.0f / (1.0f + expf(-x)); }

__device__ __forceinline__ uint32_t smem_u32(const void* p) {
    uint32_t a;
    asm("{ .reg .u64 t; cvta.to.shared.u64 t, %1; cvt.u32.u64 %0, t; }" : "=r"(a) : "l"(p));
    return a;
}
__device__ __forceinline__ uint32_t to_tf32(float x) {
    uint32_t u;
    asm("cvt.rna.tf32.f32 %0, %1;" : "=r"(u) : "f"(x));
    return u;
}
#define CP_ASYNC16(dst, src) \
    asm volatile("cp.async.cg.shared.global [%0], [%1], 16;" :: "r"(dst), "l"(src) : "memory")
#define CP_COMMIT()  asm volatile("cp.async.commit_group;" ::: "memory")
#define CP_WAIT(n)   asm volatile("cp.async.wait_group %0;" :: "n"(n) : "memory")

// ---------------- TF32 mma.sync GEMM: C[M,N] = A[M,K] @ B[N,K]^T (+bias[N]) (+Dadd) ---------
// Tile 128x128, 256 threads = 8 warps (2m x 4n), warp tile 64x32.
// Requires M%128==0, N%128==0, K%32==0, 16B-aligned rows.
__global__ __launch_bounds__(256, 2)
void gemm_mma_kernel(const float* __restrict__ A, const float* __restrict__ B,
                     const float* __restrict__ bias, const float* __restrict__ Dadd,
                     float* __restrict__ C, int N, int K)
{
    extern __shared__ ALN float smem[];     // [2][A 128*36 | B 128*36]

    const int tid = threadIdx.x;
    const int lane = tid & 31, wid = tid >> 5;
    const int wm = wid & 1, wn = wid >> 1;  // warp tile: rows wm*64, cols wn*32
    const int bx = blockIdx.x, by = blockIdx.y;

    const float* Abase = A + (size_t)(by * 128) * K;
    const float* Bbase = B + (size_t)(bx * 128) * K;

    // staging map: 4 float4 slots per thread per matrix
    const int srow = tid >> 1;              // not used; keep explicit mapping below

    float acc[4][4][4];
#pragma unroll
    for (int i = 0; i < 4; i++)
#pragma unroll
        for (int j = 0; j < 4; j++)
#pragma unroll
            for (int q = 0; q < 4; q++) acc[i][j][q] = 0.0f;

    const int nkt = K >> 5;

    // ---- issue chunk 0 ----
    {
        float* dst = smem;                  // buf 0
        const float* Ak = Abase;
        const float* Bk = Bbase;
#pragma unroll
        for (int i = 0; i < 4; i++) {
            int f = tid + i * 256;          // 0..1023
            int row = f >> 3, c4 = f & 7;
            uint32_t da = smem_u32(dst + row * RPAD + c4 * 4);
            CP_ASYNC16(da, Ak + (size_t)row * K + c4 * 4);
            uint32_t db = smem_u32(dst + ABUF + row * RPAD + c4 * 4);
            CP_ASYNC16(db, Bk + (size_t)row * K + c4 * 4);
        }
        CP_COMMIT();
    }

    for (int kt = 0; kt < nkt; kt++) {
        if (kt + 1 < nkt) {                 // issue next chunk into the other buffer
            float* dst = smem + ((kt + 1) & 1) * BUFSZ;
            const float* Ak = Abase + (kt + 1) * KCH;
            const float* Bk = Bbase + (kt + 1) * KCH;
#pragma unroll
            for (int i = 0; i < 4; i++) {
                int f = tid + i * 256;
                int row = f >> 3, c4 = f & 7;
                uint32_t da = smem_u32(dst + row * RPAD + c4 * 4);
                CP_ASYNC16(da, Ak + (size_t)row * K + c4 * 4);
                uint32_t db = smem_u32(dst + ABUF + row * RPAD + c4 * 4);
                CP_ASYNC16(db, Bk + (size_t)row * K + c4 * 4);
            }
            CP_COMMIT();
            CP_WAIT(1);                     // chunk kt has landed
        } else {
            CP_WAIT(0);
        }
        __syncthreads();

        const float* As = smem + (kt & 1) * BUFSZ;
        const float* Bs = As + ABUF;

#pragma unroll
        for (int kk = 0; kk < 4; kk++) {
            const int k0 = kk * 8 + (lane & 3);
            const int rA = wm * 64 + (lane >> 2);
            uint32_t a[4][4];
#pragma unroll
            for (int ms = 0; ms < 4; ms++) {
                const float* ap = As + (rA + ms * 16) * RPAD + k0;
                a[ms][0] = to_tf32(ap[0]);
                a[ms][1] = to_tf32(ap[8 * RPAD]);
                a[ms][2] = to_tf32(ap[4]);
                a[ms][3] = to_tf32(ap[8 * RPAD + 4]);
            }
            uint32_t b[4][2];
            const int nB = wn * 32 + (lane >> 2);
#pragma unroll
            for (int ns = 0; ns < 4; ns++) {
                const float* bp = Bs + (nB + ns * 8) * RPAD + k0;
                b[ns][0] = to_tf32(bp[0]);
                b[ns][1] = to_tf32(bp[4]);
            }
#pragma unroll
            for (int ms = 0; ms < 4; ms++)
#pragma unroll
                for (int ns = 0; ns < 4; ns++) {
                    asm volatile(
                        "mma.sync.aligned.m16n8k8.row.col.f32.tf32.tf32.f32 "
                        "{%0,%1,%2,%3}, {%4,%5,%6,%7}, {%8,%9}, {%0,%1,%2,%3};"
                        : "+f"(acc[ms][ns][0]), "+f"(acc[ms][ns][1]),
                          "+f"(acc[ms][ns][2]), "+f"(acc[ms][ns][3])
                        : "r"(a[ms][0]), "r"(a[ms][1]), "r"(a[ms][2]), "r"(a[ms][3]),
                          "r"(b[ns][0]), "r"(b[ns][1]));
                }
        }
        __syncthreads();
    }

    // ---- epilogue ----
#pragma unroll
    for (int ms = 0; ms < 4; ms++) {
        int row = by * 128 + wm * 64 + ms * 16 + (lane >> 2);
#pragma unroll
        for (int ns = 0; ns < 4; ns++) {
            int col = bx * 128 + wn * 32 + ns * 8 + (lane & 3) * 2;
            float2 bb = make_float2(0.f, 0.f);
            if (bias) bb = *(const float2*)(bias + col);
            {
                float2 v = make_float2(acc[ms][ns][0] + bb.x, acc[ms][ns][1] + bb.y);
                if (Dadd) {
                    float2 dd = *(const float2*)(Dadd + (size_t)row * N + col);
                    v.x += dd.x; v.y += dd.y;
                }
                *(float2*)(C + (size_t)row * N + col) = v;
            }
            {
                float2 v = make_float2(acc[ms][ns][2] + bb.x, acc[ms][ns][3] + bb.y);
                if (Dadd) {
                    float2 dd = *(const float2*)(Dadd + (size_t)(row + 8) * N + col);
                    v.x += dd.x; v.y += dd.y;
                }
                *(float2*)(C + (size_t)(row + 8) * N + col) = v;
            }
        }
    }
    (void)srow;
}

// ---------------- small utility kernels ----------------
__global__ void zero_kernel(float* p, size_t n) {
    size_t i = (size_t)blockIdx.x * blockDim.x + threadIdx.x;
    if (i < n) p[i] = 0.0f;
}

__global__ void zero_ctr_kernel() {
    if (threadIdx.x < 2) g_ctr[threadIdx.x] = 0u;
}

__global__ void pack_wihc_kernel(const float* __restrict__ src, float* __restrict__ dst) {
    int n = blockIdx.x;
    for (int k = threadIdx.x; k < CDP; k += blockDim.x)
        dst[n * CDP + k] = (k < CD) ? src[n * CD + k] : 0.0f;
}

__global__ void pack_wihw_kernel(const float* __restrict__ src, float* __restrict__ dst) {
    int n = blockIdx.x;
    for (int k = threadIdx.x; k < WDINP; k += blockDim.x)
        dst[n * WDINP + k] = (k < WDIN) ? src[n * WDIN + k] : 0.0f;
}

__global__ void bias_sum_kernel(const float* __restrict__ a, const float* __restrict__ b,
                                float* __restrict__ o) {
    int i = blockIdx.x * blockDim.x + threadIdx.x;
    if (i < G4) o[i] = a[i] + b[i];
}

__global__ void gather_char_kernel(const int* __restrict__ cseq, const float* __restrict__ cemb,
                                   float* __restrict__ Xc) {
    int id = blockIdx.x;            // id = t*W + w
    int t = id >> 13;
    int w = id & (W - 1);
    int ci = cseq[w * LC + t];
    float* dst = Xc + (size_t)id * CDP;
    const float* src = cemb + (size_t)ci * CD;
    for (int k = threadIdx.x; k < CDP; k += blockDim.x)
        dst[k] = (k < CD) ? src[k] : 0.0f;
}

__global__ void gather_word_kernel(const int* __restrict__ wseq, const float* __restrict__ wemb,
                                   const float* __restrict__ Hf, const float* __restrict__ Hb,
                                   float* __restrict__ WX) {
    int w = blockIdx.x;
    int wi = wseq[w];
    float* dst = WX + (size_t)w * WDINP;
    for (int k = threadIdx.x; k < WDINP; k += blockDim.x) {
        float v;
        if (k < WD)            v = wemb[(size_t)wi * WD + k];
        else if (k < WD + HH)  v = Hf[(size_t)w * HH + (k - WD)];
        else if (k < WDIN)     v = Hb[(size_t)w * HH + (k - WD - HH)];
        else                   v = 0.0f;
        dst[k] = v;
    }
}

// ---------------- char LSTM pointwise update (masked) ----------------
__global__ void char_update_kernel(const float* __restrict__ Gm, const int* __restrict__ lens,
                                   float* __restrict__ Hs, float* __restrict__ Cs, int t)
{
    int idx = blockIdx.x * blockDim.x + threadIdx.x;   // w*256 + j
    int w = idx >> 8;
    int j = idx & 255;
    if (t >= lens[w]) return;
    const float* gr = Gm + (size_t)w * G4;
    float gi = gr[j], gf = gr[256 + j], gg = gr[512 + j], go = gr[768 + j];
    float c = Cs[idx];
    float cn = sigmoidf_(gf) * c + sigmoidf_(gi) * tanhf(gg);
    float hn = sigmoidf_(go) * tanhf(cn);
    Hs[idx] = hn;
    Cs[idx] = cn;
}

// ---------------- sequential word BiLSTM: persistent kernel, 16 co-resident CTAs ----------------
__global__ __launch_bounds__(256, 1) void word_lstm_kernel(
    const float* __restrict__ XGw,
    const float* __restrict__ WhhF, const float* __restrict__ WhhB,
    float* __restrict__ OUT)
{
    int bid = blockIdx.x;
    int d = bid >> 3;
    int b = bid & 7;
    int tid = threadIdx.x;
    int half = tid >> 7;
    int r = tid & 127;
    int g = r >> 5, jj = r & 31;
    int rowg = g * 256 + b * 32 + jj;

    const float* Whh = d ? WhhB : WhhF;
    const float* xgbase = XGw + (size_t)d * W * G4;

    __shared__ ALN float h_sh[HH];
    __shared__ ALN float psum[256];
    __shared__ ALN float gsh[128];

    float wreg[128];
#pragma unroll
    for (int i = 0; i < 128; i += 4) {
        float4 v = *(const float4*)(Whh + (size_t)rowg * HH + half * 128 + i);
        wreg[i] = v.x; wreg[i + 1] = v.y; wreg[i + 2] = v.z; wreg[i + 3] = v.w;
    }
    if (tid < 64) *(float4*)&h_sh[tid * 4] = make_float4(0.f, 0.f, 0.f, 0.f);
    float c = 0.0f;
    __syncthreads();

    for (int t = 0; t < W; t++) {
        int p = d ? (W - 1 - t) : t;
        float xg = __ldg(xgbase + (size_t)p * G4 + rowg);

        float s0 = 0.f, s1 = 0.f, s2 = 0.f, s3 = 0.f;
#pragma unroll
        for (int i = 0; i < 128; i += 4) {
            float4 h4 = *(const float4*)&h_sh[half * 128 + i];
            s0 = fmaf(h4.x, wreg[i],     s0);
            s1 = fmaf(h4.y, wreg[i + 1], s1);
            s2 = fmaf(h4.z, wreg[i + 2], s2);
            s3 = fmaf(h4.w, wreg[i + 3], s3);
        }
        psum[tid] = (s0 + s1) + (s2 + s3);
        __syncthreads();

        if (tid < 128) gsh[tid] = xg + psum[tid] + psum[tid + 128];
        __syncthreads();

        int buf = (t + 1) & 1;
        if (tid < 32) {
            float gi = gsh[tid], gf = gsh[32 + tid], gg = gsh[64 + tid], go = gsh[96 + tid];
            float cn = sigmoidf_(gf) * c + sigmoidf_(gi) * tanhf(gg);
            c = cn;
            float hn = sigmoidf_(go) * tanhf(cn);
            g_hex[d][buf][b * 32 + tid] = hn;
            OUT[(size_t)p * HD + d * HH + b * 32 + tid] = hn;
            __threadfence();
        }
        __syncthreads();

        if (tid == 0) {
            __threadfence();
            atomicAdd((unsigned*)&g_ctr[d], 1u);
            unsigned target = 8u * (unsigned)(t + 1);
            while (*(volatile unsigned*)&g_ctr[d] < target) { }
            __threadfence();
        }
        __syncthreads();

        if (tid < 64) {
            int i4 = tid * 4;
            float x0 = g_hex[d][buf][i4];
            float x1 = g_hex[d][buf][i4 + 1];
            float x2 = g_hex[d][buf][i4 + 2];
            float x3 = g_hex[d][buf][i4 + 3];
            *(float4*)&h_sh[i4] = make_float4(x0, x1, x2, x3);
        }
        __syncthreads();
    }
}

// ---------------- heads: logits + log_softmax ----------------
__global__ __launch_bounds__(128) void heads_kernel(
    const float* __restrict__ OUT,
    const float* __restrict__ Wp, const float* __restrict__ bp,
    const float* __restrict__ Wp2, const float* __restrict__ bp2,
    float* __restrict__ out)
{
    int w = blockIdx.x;
    __shared__ ALN float osh[HD];
    __shared__ ALN float lsh[T1 + T2];
    int tid = threadIdx.x;
    int lane = tid & 31, wid = tid >> 5;

    for (int k = tid; k < HD; k += 128) osh[k] = OUT[(size_t)w * HD + k];
    __syncthreads();

    for (int l = wid; l < T1 + T2; l += 4) {
        const float* wr = (l < T1) ? (Wp + (size_t)l * HD) : (Wp2 + (size_t)(l - T1) * HD);
        float s = 0.0f;
#pragma unroll 4
        for (int k = lane; k < HD; k += 32) s = fmaf(osh[k], wr[k], s);
#pragma unroll
        for (int o = 16; o; o >>= 1) s += __shfl_xor_sync(0xFFFFFFFFu, s, o);
        if (lane == 0) lsh[l] = s + ((l < T1) ? bp[l] : bp2[l - T1]);
    }
    __syncthreads();

    if (wid < 2) {
        int T = (wid == 0) ? T1 : T2;
        int base = (wid == 0) ? 0 : T1;
        float* ob = (wid == 0) ? (out + (size_t)w * T1)
                               : (out + (size_t)W * T1 + (size_t)w * T2);
        float mx = -1e30f;
        for (int l = lane; l < T; l += 32) mx = fmaxf(mx, lsh[base + l]);
#pragma unroll
        for (int o = 16; o; o >>= 1) mx = fmaxf(mx, __shfl_xor_sync(0xFFFFFFFFu, mx, o));
        float se = 0.0f;
        for (int l = lane; l < T; l += 32) se += expf(lsh[base + l] - mx);
#pragma unroll
        for (int o = 16; o; o >>= 1) se += __shfl_xor_sync(0xFFFFFFFFu, se, o);
        float lz = mx + logf(se);
        for (int l = lane; l < T; l += 32) ob[l] = lsh[base + l] - lz;
    }
}

// ---------------- host orchestration ----------------
static void* sym(const void* s) {
    void* p = nullptr;
    cudaGetSymbolAddress(&p, s);
    return p;
}

extern "C" void kernel_launch(void* const* d_in, const int* in_sizes, int n_in,
                              void* d_out, int out_size)
{
    const int*   wseq  = (const int*)d_in[0];
    const int*   cseq  = (const int*)d_in[1];
    const int*   lens  = (const int*)d_in[2];
    const float* cemb  = (const float*)d_in[3];
    const float* wemb  = (const float*)d_in[4];
    const float* cfWih = (const float*)d_in[5];
    const float* cfWhh = (const float*)d_in[6];
    const float* cfbih = (const float*)d_in[7];
    const float* cfbhh = (const float*)d_in[8];
    const float* cbWih = (const float*)d_in[9];
    const float* cbWhh = (const float*)d_in[10];
    const float* cbbih = (const float*)d_in[11];
    const float* cbbhh = (const float*)d_in[12];
    const float* wfWih = (const float*)d_in[13];
    const float* wfWhh = (const float*)d_in[14];
    const float* wfbih = (const float*)d_in[15];
    const float* wfbhh = (const float*)d_in[16];
    const float* wbWih = (const float*)d_in[17];
    const float* wbWhh = (const float*)d_in[18];
    const float* wbbih = (const float*)d_in[19];
    const float* wbbhh = (const float*)d_in[20];
    const float* Wp    = (const float*)d_in[21];
    const float* bp    = (const float*)d_in[22];
    const float* Wp2   = (const float*)d_in[23];
    const float* bp2   = (const float*)d_in[24];
    float* outp = (float*)d_out;

    float* Xc   = (float*)sym(g_Xc);
    float* XG   = (float*)sym(g_XG);
    float* G    = (float*)sym(g_G);
    float* Hf   = (float*)sym(g_Hf);
    float* Hb   = (float*)sym(g_Hb);
    float* Cc   = (float*)sym(g_Cc);
    float* WX   = (float*)sym(g_WX);
    float* XGw  = (float*)sym(g_XGw);
    float* OUT  = (float*)sym(g_OUT);
    float* WihC = (float*)sym(g_WihC);
    float* WihW = (float*)sym(g_WihW);
    float* bias = (float*)sym(g_bias);

    cudaFuncSetAttribute(gemm_mma_kernel, cudaFuncAttributeMaxDynamicSharedMemorySize,
                         GEMM_SMEM_BYTES);

    // ---- pack weights / biases ----
    pack_wihc_kernel<<<G4, 128>>>(cfWih, WihC + 0 * (size_t)G4 * CDP);
    pack_wihc_kernel<<<G4, 128>>>(cbWih, WihC + 1 * (size_t)G4 * CDP);
    pack_wihw_kernel<<<G4, 256>>>(wfWih, WihW + 0 * (size_t)G4 * WDINP);
    pack_wihw_kernel<<<G4, 256>>>(wbWih, WihW + 1 * (size_t)G4 * WDINP);
    bias_sum_kernel<<<4, 256>>>(cfbih, cfbhh, bias + 0 * G4);
    bias_sum_kernel<<<4, 256>>>(cbbih, cbbhh, bias + 1 * G4);
    bias_sum_kernel<<<4, 256>>>(wfbih, wfbhh, bias + 2 * G4);
    bias_sum_kernel<<<4, 256>>>(wbbih, wbbhh, bias + 3 * G4);

    // ---- gather char embeddings ----
    gather_char_kernel<<<LC * W, 128>>>(cseq, cemb, Xc);

    // ---- char BiLSTM, one direction at a time ----
    const size_t nWH = (size_t)W * HH;
    for (int dir = 0; dir < 2; dir++) {
        float* Hdir = dir ? Hb : Hf;
        const float* Whh = dir ? cbWhh : cfWhh;
        zero_kernel<<<(unsigned)((nWH + 255) / 256), 256>>>(Hdir, nWH);
        zero_kernel<<<(unsigned)((nWH + 255) / 256), 256>>>(Cc, nWH);

        // XG = Xc @ WihT + (bih+bhh):  M = 131072, K = 128, N = 1024
        gemm_mma_kernel<<<dim3(G4 / 128, (LC * W) / 128), 256, GEMM_SMEM_BYTES>>>(
            Xc, WihC + (size_t)dir * G4 * CDP, bias + (size_t)dir * G4, nullptr, XG, G4, CDP);

        for (int s = 0; s < LC; s++) {
            int t = dir ? (LC - 1 - s) : s;
            // G = H @ WhhT + XG[t]:  M = 8192, K = 256, N = 1024
            gemm_mma_kernel<<<dim3(G4 / 128, W / 128), 256, GEMM_SMEM_BYTES>>>(
                Hdir, Whh, nullptr, XG + (size_t)t * W * G4, G, G4, HH);
            char_update_kernel<<<(W * HH) / 256, 256>>>(G, lens, Hdir, Cc, t);
        }
    }

    // ---- word-level input ----
    gather_word_kernel<<<W, 256>>>(wseq, wemb, Hf, Hb, WX);
    // XGw = WX @ WihT + bias:  M = 8192, K = 832, N = 1024
    gemm_mma_kernel<<<dim3(G4 / 128, W / 128), 256, GEMM_SMEM_BYTES>>>(
        WX, WihW + 0 * (size_t)G4 * WDINP, bias + 2 * G4, nullptr, XGw, G4, WDINP);
    gemm_mma_kernel<<<dim3(G4 / 128, W / 128), 256, GEMM_SMEM_BYTES>>>(
        WX, WihW + 1 * (size_t)G4 * WDINP, bias + 3 * G4, nullptr, XGw + (size_t)W * G4, G4, WDINP);

    // ---- sequential word BiLSTM (both directions concurrently) ----
    zero_ctr_kernel<<<1, 32>>>();
    word_lstm_kernel<<<16, 256>>>(XGw, wfWhh, wbWhh, OUT);

    // ---- heads + log_softmax ----
    heads_kernel<<<W, 128>>>(OUT, Wp, bp, Wp2, bp2, outp);

    (void)in_sizes; (void)n_in; (void)out_size;
}

// round 5
// speedup vs baseline: 1.2778x; 1.1868x over previous
#include <cuda_runtime.h>
#include <math.h>
#include <stdint.h>

// ---------------- problem constants ----------------
#define W     8192      // words
#define LC    16        // chars per word (padded)
#define CD    100       // char emb dim
#define CDP   128       // padded to %32 for tensor GEMM
#define WD    300       // word emb dim
#define HD    512       // hidden dim (bi)
#define HH    256       // per-direction hidden
#define G4    1024      // 4*HH gates
#define WDIN  812       // WD + HD
#define WDINP 832       // padded to %32
#define T1    48
#define T2    32

#define NCTA_DIR 16     // word-lstm CTAs per direction
#define CELLS    16     // cells per CTA (HH / NCTA_DIR)

#define ALN __align__(16)

// smem layout constants for GEMM (floats)
#define KCH   32
#define RPAD  36
#define ABUF  (128 * RPAD)
#define BUFSZ (2 * ABUF)
#define GEMM_SMEM_BYTES (2 * BUFSZ * 4)   // 73728 B

// ---------------- static device scratch (no cudaMalloc allowed) ----------------
__device__ ALN float g_Xc[(size_t)LC * W * CDP];
__device__ ALN float g_XG[(size_t)LC * W * G4];
__device__ ALN float g_G[(size_t)W * G4];
__device__ ALN float g_Hf[(size_t)W * HH];
__device__ ALN float g_Hb[(size_t)W * HH];
__device__ ALN float g_Cc[(size_t)W * HH];
__device__ ALN float g_WX[(size_t)W * WDINP];
__device__ ALN float g_XGw[(size_t)2 * W * G4];
__device__ ALN float g_OUT[(size_t)W * HD];
__device__ ALN float g_WihC[2][G4 * CDP];
__device__ ALN float g_WihW[2][G4 * WDINP];
__device__ ALN float g_bias[4][G4];
__device__ ALN float g_hex[2][2][HH];              // [dir][buf][256] h exchange
__device__ ALN unsigned g_flag[2][NCTA_DIR][32];   // per-CTA step flags, 128B apart

__device__ __forceinline__ float sigmoidf_(float x) { return 1.0f / (1.0f + expf(-x)); }

__device__ __forceinline__ uint32_t smem_u32(const void* p) {
    uint32_t a;
    asm("{ .reg .u64 t; cvta.to.shared.u64 t, %1; cvt.u32.u64 %0, t; }" : "=r"(a) : "l"(p));
    return a;
}
__device__ __forceinline__ uint32_t to_tf32(float x) {
    uint32_t u;
    asm("cvt.rna.tf32.f32 %0, %1;" : "=r"(u) : "f"(x));
    return u;
}
__device__ __forceinline__ unsigned ld_acq_u32(const unsigned* p) {
    unsigned v;
    asm volatile("ld.acquire.gpu.u32 %0, [%1];" : "=r"(v) : "l"(p) : "memory");
    return v;
}
__device__ __forceinline__ void st_rel_u32(unsigned* p, unsigned v) {
    asm volatile("st.release.gpu.u32 [%0], %1;" :: "l"(p), "r"(v) : "memory");
}
#define CP_ASYNC16(dst, src) \
    asm volatile("cp.async.cg.shared.global [%0], [%1], 16;" :: "r"(dst), "l"(src) : "memory")
#define CP_COMMIT()  asm volatile("cp.async.commit_group;" ::: "memory")
#define CP_WAIT(n)   asm volatile("cp.async.wait_group %0;" :: "n"(n) : "memory")

// ---------------- TF32 mma.sync GEMM: C[M,N] = A[M,K] @ B[N,K]^T (+bias[N]) (+Dadd) ---------
__global__ __launch_bounds__(256, 2)
void gemm_mma_kernel(const float* __restrict__ A, const float* __restrict__ B,
                     const float* __restrict__ bias, const float* __restrict__ Dadd,
                     float* __restrict__ C, int N, int K)
{
    extern __shared__ ALN float smem[];

    const int tid = threadIdx.x;
    const int lane = tid & 31, wid = tid >> 5;
    const int wm = wid & 1, wn = wid >> 1;
    const int bx = blockIdx.x, by = blockIdx.y;

    const float* Abase = A + (size_t)(by * 128) * K;
    const float* Bbase = B + (size_t)(bx * 128) * K;

    float acc[4][4][4];
#pragma unroll
    for (int i = 0; i < 4; i++)
#pragma unroll
        for (int j = 0; j < 4; j++)
#pragma unroll
            for (int q = 0; q < 4; q++) acc[i][j][q] = 0.0f;

    const int nkt = K >> 5;

    {
        float* dst = smem;
#pragma unroll
        for (int i = 0; i < 4; i++) {
            int f = tid + i * 256;
            int row = f >> 3, c4 = f & 7;
            CP_ASYNC16(smem_u32(dst + row * RPAD + c4 * 4), Abase + (size_t)row * K + c4 * 4);
            CP_ASYNC16(smem_u32(dst + ABUF + row * RPAD + c4 * 4), Bbase + (size_t)row * K + c4 * 4);
        }
        CP_COMMIT();
    }

    for (int kt = 0; kt < nkt; kt++) {
        if (kt + 1 < nkt) {
            float* dst = smem + ((kt + 1) & 1) * BUFSZ;
            const float* Ak = Abase + (kt + 1) * KCH;
            const float* Bk = Bbase + (kt + 1) * KCH;
#pragma unroll
            for (int i = 0; i < 4; i++) {
                int f = tid + i * 256;
                int row = f >> 3, c4 = f & 7;
                CP_ASYNC16(smem_u32(dst + row * RPAD + c4 * 4), Ak + (size_t)row * K + c4 * 4);
                CP_ASYNC16(smem_u32(dst + ABUF + row * RPAD + c4 * 4), Bk + (size_t)row * K + c4 * 4);
            }
            CP_COMMIT();
            CP_WAIT(1);
        } else {
            CP_WAIT(0);
        }
        __syncthreads();

        const float* As = smem + (kt & 1) * BUFSZ;
        const float* Bs = As + ABUF;

#pragma unroll
        for (int kk = 0; kk < 4; kk++) {
            const int k0 = kk * 8 + (lane & 3);
            const int rA = wm * 64 + (lane >> 2);
            uint32_t a[4][4];
#pragma unroll
            for (int ms = 0; ms < 4; ms++) {
                const float* ap = As + (rA + ms * 16) * RPAD + k0;
                a[ms][0] = to_tf32(ap[0]);
                a[ms][1] = to_tf32(ap[8 * RPAD]);
                a[ms][2] = to_tf32(ap[4]);
                a[ms][3] = to_tf32(ap[8 * RPAD + 4]);
            }
            uint32_t b[4][2];
            const int nB = wn * 32 + (lane >> 2);
#pragma unroll
            for (int ns = 0; ns < 4; ns++) {
                const float* bp = Bs + (nB + ns * 8) * RPAD + k0;
                b[ns][0] = to_tf32(bp[0]);
                b[ns][1] = to_tf32(bp[4]);
            }
#pragma unroll
            for (int ms = 0; ms < 4; ms++)
#pragma unroll
                for (int ns = 0; ns < 4; ns++) {
                    asm volatile(
                        "mma.sync.aligned.m16n8k8.row.col.f32.tf32.tf32.f32 "
                        "{%0,%1,%2,%3}, {%4,%5,%6,%7}, {%8,%9}, {%0,%1,%2,%3};"
                        : "+f"(acc[ms][ns][0]), "+f"(acc[ms][ns][1]),
                          "+f"(acc[ms][ns][2]), "+f"(acc[ms][ns][3])
                        : "r"(a[ms][0]), "r"(a[ms][1]), "r"(a[ms][2]), "r"(a[ms][3]),
                          "r"(b[ns][0]), "r"(b[ns][1]));
                }
        }
        __syncthreads();
    }

#pragma unroll
    for (int ms = 0; ms < 4; ms++) {
        int row = by * 128 + wm * 64 + ms * 16 + (lane >> 2);
#pragma unroll
        for (int ns = 0; ns < 4; ns++) {
            int col = bx * 128 + wn * 32 + ns * 8 + (lane & 3) * 2;
            float2 bb = make_float2(0.f, 0.f);
            if (bias) bb = *(const float2*)(bias + col);
            {
                float2 v = make_float2(acc[ms][ns][0] + bb.x, acc[ms][ns][1] + bb.y);
                if (Dadd) {
                    float2 dd = *(const float2*)(Dadd + (size_t)row * N + col);
                    v.x += dd.x; v.y += dd.y;
                }
                *(float2*)(C + (size_t)row * N + col) = v;
            }
            {
                float2 v = make_float2(acc[ms][ns][2] + bb.x, acc[ms][ns][3] + bb.y);
                if (Dadd) {
                    float2 dd = *(const float2*)(Dadd + (size_t)(row + 8) * N + col);
                    v.x += dd.x; v.y += dd.y;
                }
                *(float2*)(C + (size_t)(row + 8) * N + col) = v;
            }
        }
    }
}

// ---------------- small utility kernels ----------------
__global__ void zero_kernel(float* p, size_t n) {
    size_t i = (size_t)blockIdx.x * blockDim.x + threadIdx.x;
    if (i < n) p[i] = 0.0f;
}

__global__ void zero_flags_kernel() {
    int i = blockIdx.x * blockDim.x + threadIdx.x;   // 2*16*32 = 1024 entries
    if (i < 2 * NCTA_DIR * 32) ((unsigned*)g_flag)[i] = 0u;
}

__global__ void pack_wihc_kernel(const float* __restrict__ src, float* __restrict__ dst) {
    int n = blockIdx.x;
    for (int k = threadIdx.x; k < CDP; k += blockDim.x)
        dst[n * CDP + k] = (k < CD) ? src[n * CD + k] : 0.0f;
}

__global__ void pack_wihw_kernel(const float* __restrict__ src, float* __restrict__ dst) {
    int n = blockIdx.x;
    for (int k = threadIdx.x; k < WDINP; k += blockDim.x)
        dst[n * WDINP + k] = (k < WDIN) ? src[n * WDIN + k] : 0.0f;
}

__global__ void bias_sum_kernel(const float* __restrict__ a, const float* __restrict__ b,
                                float* __restrict__ o) {
    int i = blockIdx.x * blockDim.x + threadIdx.x;
    if (i < G4) o[i] = a[i] + b[i];
}

__global__ void gather_char_kernel(const int* __restrict__ cseq, const float* __restrict__ cemb,
                                   float* __restrict__ Xc) {
    int id = blockIdx.x;            // id = t*W + w
    int t = id >> 13;
    int w = id & (W - 1);
    int ci = cseq[w * LC + t];
    float* dst = Xc + (size_t)id * CDP;
    const float* src = cemb + (size_t)ci * CD;
    for (int k = threadIdx.x; k < CDP; k += blockDim.x)
        dst[k] = (k < CD) ? src[k] : 0.0f;
}

__global__ void gather_word_kernel(const int* __restrict__ wseq, const float* __restrict__ wemb,
                                   const float* __restrict__ Hf, const float* __restrict__ Hb,
                                   float* __restrict__ WX) {
    int w = blockIdx.x;
    int wi = wseq[w];
    float* dst = WX + (size_t)w * WDINP;
    for (int k = threadIdx.x; k < WDINP; k += blockDim.x) {
        float v;
        if (k < WD)            v = wemb[(size_t)wi * WD + k];
        else if (k < WD + HH)  v = Hf[(size_t)w * HH + (k - WD)];
        else if (k < WDIN)     v = Hb[(size_t)w * HH + (k - WD - HH)];
        else                   v = 0.0f;
        dst[k] = v;
    }
}

// ---------------- char LSTM pointwise update (masked) ----------------
__global__ void char_update_kernel(const float* __restrict__ Gm, const int* __restrict__ lens,
                                   float* __restrict__ Hs, float* __restrict__ Cs, int t)
{
    int idx = blockIdx.x * blockDim.x + threadIdx.x;   // w*256 + j
    int w = idx >> 8;
    int j = idx & 255;
    if (t >= lens[w]) return;
    const float* gr = Gm + (size_t)w * G4;
    float gi = gr[j], gf = gr[256 + j], gg = gr[512 + j], go = gr[768 + j];
    float c = Cs[idx];
    float cn = sigmoidf_(gf) * c + sigmoidf_(gi) * tanhf(gg);
    float hn = sigmoidf_(go) * tanhf(cn);
    Hs[idx] = hn;
    Cs[idx] = cn;
}

// ---------------- sequential word BiLSTM: flag-synced persistent CTAs ----------------
// grid = 32 CTAs: d = bid/16 (direction), b = bid%16 (cells [b*16, b*16+16)).
// 256 threads: tid = q*64 + r; q = quarter of h (64 floats), r = gate row (g*16+jj).
// Thread owns Whh[g*256 + b*16 + jj][q*64 .. q*64+64) in registers.
// Sync: per-CTA monotonic flag (release store) + acquire polling by warp 1,
// overlapped with warp 0's gate computation. h exchanged via double-buffered
// global array, read back with __ldcg (L1 bypass). Max CTA skew = 1 step.
__global__ __launch_bounds__(256, 1) void word_lstm_kernel(
    const float* __restrict__ XGw,
    const float* __restrict__ WhhF, const float* __restrict__ WhhB,
    float* __restrict__ OUT)
{
    const int d = blockIdx.x >> 4;
    const int b = blockIdx.x & 15;
    const int tid = threadIdx.x;
    const int q = tid >> 6;
    const int r = tid & 63;
    const int g = r >> 4, jj = r & 15;
    const int rowg = (g << 8) + b * CELLS + jj;

    const float* Whh = d ? WhhB : WhhF;
    const float* xgbase = XGw + (size_t)d * W * G4;

    __shared__ ALN float h_sh[2][HH];
    __shared__ ALN float psum[256];
    __shared__ ALN float gsh[64];

    float wreg[64];
#pragma unroll
    for (int i = 0; i < 64; i += 4) {
        float4 v = *(const float4*)(Whh + (size_t)rowg * HH + q * 64 + i);
        wreg[i] = v.x; wreg[i + 1] = v.y; wreg[i + 2] = v.z; wreg[i + 3] = v.w;
    }
    ((float*)h_sh)[tid] = 0.0f;
    ((float*)h_sh)[tid + 256] = 0.0f;
    float c = 0.0f;
    __syncthreads();

    float xg_cur = __ldg(xgbase + (size_t)(d ? (W - 1) : 0) * G4 + rowg);

    for (int t = 0; t < W; t++) {
        const int p = d ? (W - 1 - t) : t;
        const int buf = t & 1;
        const int nb = buf ^ 1;

        // prefetch next step's input gate (latency hidden under this step)
        float xg_next = 0.0f;
        if (t + 1 < W) {
            int pn = d ? (W - 2 - t) : (t + 1);
            xg_next = __ldg(xgbase + (size_t)pn * G4 + rowg);
        }

        // matvec partial: 64 MACs from broadcast smem h
        const float* hb = &h_sh[buf][q * 64];
        float s0 = 0.f, s1 = 0.f, s2 = 0.f, s3 = 0.f;
#pragma unroll
        for (int i = 0; i < 64; i += 4) {
            float4 h4 = *(const float4*)(hb + i);
            s0 = fmaf(h4.x, wreg[i],     s0);
            s1 = fmaf(h4.y, wreg[i + 1], s1);
            s2 = fmaf(h4.z, wreg[i + 2], s2);
            s3 = fmaf(h4.w, wreg[i + 3], s3);
        }
        psum[tid] = (s0 + s1) + (s2 + s3);
        __syncthreads();

        // warps 0-1: finish gate pre-activations, then split roles
        if (tid < 64) {
            gsh[r] = xg_cur + ((psum[r] + psum[64 + r]) + (psum[128 + r] + psum[192 + r]));
            asm volatile("bar.sync 1, 64;" ::: "memory");   // warps 0,1 only
        }

        if (tid < 32) {
            // warp 0: gates + h publish
            if (tid < CELLS) {
                float gi = gsh[tid], gf = gsh[16 + tid], gg = gsh[32 + tid], go = gsh[48 + tid];
                float cn = sigmoidf_(gf) * c + sigmoidf_(gi) * tanhf(gg);
                c = cn;
                float hn = sigmoidf_(go) * tanhf(cn);
                g_hex[d][nb][b * CELLS + tid] = hn;
                OUT[(size_t)p * HD + d * HH + b * CELLS + tid] = hn;
            }
            __syncwarp();
            if (tid == 0) {
                __threadfence();                     // order h stores (gpu scope)
                st_rel_u32(&g_flag[d][b][0], (unsigned)(t + 1));
            }
        } else if (tid < 48) {
            // warp 1 lanes 0-15: poll all 16 CTA flags (overlaps warp 0's work)
            const unsigned target = (unsigned)(t + 1);
            while (ld_acq_u32(&g_flag[d][tid - 32][0]) < target) { }
        }
        __syncthreads();

        // load all 256 h values for next step (L2, L1-bypassing)
        if (tid < 64) {
            float4 v = __ldcg((const float4*)&g_hex[d][nb][tid * 4]);
            *(float4*)&h_sh[nb][tid * 4] = v;
        }
        __syncthreads();

        xg_cur = xg_next;
    }
}

// ---------------- heads: logits + log_softmax ----------------
__global__ __launch_bounds__(128) void heads_kernel(
    const float* __restrict__ OUT,
    const float* __restrict__ Wp, const float* __restrict__ bp,
    const float* __restrict__ Wp2, const float* __restrict__ bp2,
    float* __restrict__ out)
{
    int w = blockIdx.x;
    __shared__ ALN float osh[HD];
    __shared__ ALN float lsh[T1 + T2];
    int tid = threadIdx.x;
    int lane = tid & 31, wid = tid >> 5;

    for (int k = tid; k < HD; k += 128) osh[k] = OUT[(size_t)w * HD + k];
    __syncthreads();

    for (int l = wid; l < T1 + T2; l += 4) {
        const float* wr = (l < T1) ? (Wp + (size_t)l * HD) : (Wp2 + (size_t)(l - T1) * HD);
        float s = 0.0f;
#pragma unroll 4
        for (int k = lane; k < HD; k += 32) s = fmaf(osh[k], wr[k], s);
#pragma unroll
        for (int o = 16; o; o >>= 1) s += __shfl_xor_sync(0xFFFFFFFFu, s, o);
        if (lane == 0) lsh[l] = s + ((l < T1) ? bp[l] : bp2[l - T1]);
    }
    __syncthreads();

    if (wid < 2) {
        int T = (wid == 0) ? T1 : T2;
        int base = (wid == 0) ? 0 : T1;
        float* ob = (wid == 0) ? (out + (size_t)w * T1)
                               : (out + (size_t)W * T1 + (size_t)w * T2);
        float mx = -1e30f;
        for (int l = lane; l < T; l += 32) mx = fmaxf(mx, lsh[base + l]);
#pragma unroll
        for (int o = 16; o; o >>= 1) mx = fmaxf(mx, __shfl_xor_sync(0xFFFFFFFFu, mx, o));
        float se = 0.0f;
        for (int l = lane; l < T; l += 32) se += expf(lsh[base + l] - mx);
#pragma unroll
        for (int o = 16; o; o >>= 1) se += __shfl_xor_sync(0xFFFFFFFFu, se, o);
        float lz = mx + logf(se);
        for (int l = lane; l < T; l += 32) ob[l] = lsh[base + l] - lz;
    }
}

// ---------------- host orchestration ----------------
static void* sym(const void* s) {
    void* p = nullptr;
    cudaGetSymbolAddress(&p, s);
    return p;
}

extern "C" void kernel_launch(void* const* d_in, const int* in_sizes, int n_in,
                              void* d_out, int out_size)
{
    const int*   wseq  = (const int*)d_in[0];
    const int*   cseq  = (const int*)d_in[1];
    const int*   lens  = (const int*)d_in[2];
    const float* cemb  = (const float*)d_in[3];
    const float* wemb  = (const float*)d_in[4];
    const float* cfWih = (const float*)d_in[5];
    const float* cfWhh = (const float*)d_in[6];
    const float* cfbih = (const float*)d_in[7];
    const float* cfbhh = (const float*)d_in[8];
    const float* cbWih = (const float*)d_in[9];
    const float* cbWhh = (const float*)d_in[10];
    const float* cbbih = (const float*)d_in[11];
    const float* cbbhh = (const float*)d_in[12];
    const float* wfWih = (const float*)d_in[13];
    const float* wfWhh = (const float*)d_in[14];
    const float* wfbih = (const float*)d_in[15];
    const float* wfbhh = (const float*)d_in[16];
    const float* wbWih = (const float*)d_in[17];
    const float* wbWhh = (const float*)d_in[18];
    const float* wbbih = (const float*)d_in[19];
    const float* wbbhh = (const float*)d_in[20];
    const float* Wp    = (const float*)d_in[21];
    const float* bp    = (const float*)d_in[22];
    const float* Wp2   = (const float*)d_in[23];
    const float* bp2   = (const float*)d_in[24];
    float* outp = (float*)d_out;

    float* Xc   = (float*)sym(g_Xc);
    float* XG   = (float*)sym(g_XG);
    float* G    = (float*)sym(g_G);
    float* Hf   = (float*)sym(g_Hf);
    float* Hb   = (float*)sym(g_Hb);
    float* Cc   = (float*)sym(g_Cc);
    float* WX   = (float*)sym(g_WX);
    float* XGw  = (float*)sym(g_XGw);
    float* OUT  = (float*)sym(g_OUT);
    float* WihC = (float*)sym(g_WihC);
    float* WihW = (float*)sym(g_WihW);
    float* bias = (float*)sym(g_bias);

    cudaFuncSetAttribute(gemm_mma_kernel, cudaFuncAttributeMaxDynamicSharedMemorySize,
                         GEMM_SMEM_BYTES);

    // ---- pack weights / biases ----
    pack_wihc_kernel<<<G4, 128>>>(cfWih, WihC + 0 * (size_t)G4 * CDP);
    pack_wihc_kernel<<<G4, 128>>>(cbWih, WihC + 1 * (size_t)G4 * CDP);
    pack_wihw_kernel<<<G4, 256>>>(wfWih, WihW + 0 * (size_t)G4 * WDINP);
    pack_wihw_kernel<<<G4, 256>>>(wbWih, WihW + 1 * (size_t)G4 * WDINP);
    bias_sum_kernel<<<4, 256>>>(cfbih, cfbhh, bias + 0 * G4);
    bias_sum_kernel<<<4, 256>>>(cbbih, cbbhh, bias + 1 * G4);
    bias_sum_kernel<<<4, 256>>>(wfbih, wfbhh, bias + 2 * G4);
    bias_sum_kernel<<<4, 256>>>(wbbih, wbbhh, bias + 3 * G4);

    // ---- gather char embeddings ----
    gather_char_kernel<<<LC * W, 128>>>(cseq, cemb, Xc);

    // ---- char BiLSTM, one direction at a time ----
    const size_t nWH = (size_t)W * HH;
    for (int dir = 0; dir < 2; dir++) {
        float* Hdir = dir ? Hb : Hf;
        const float* Whh = dir ? cbWhh : cfWhh;
        zero_kernel<<<(unsigned)((nWH + 255) / 256), 256>>>(Hdir, nWH);
        zero_kernel<<<(unsigned)((nWH + 255) / 256), 256>>>(Cc, nWH);

        // XG = Xc @ WihT + (bih+bhh):  M = 131072, K = 128, N = 1024
        gemm_mma_kernel<<<dim3(G4 / 128, (LC * W) / 128), 256, GEMM_SMEM_BYTES>>>(
            Xc, WihC + (size_t)dir * G4 * CDP, bias + (size_t)dir * G4, nullptr, XG, G4, CDP);

        for (int s = 0; s < LC; s++) {
            int t = dir ? (LC - 1 - s) : s;
            // G = H @ WhhT + XG[t]:  M = 8192, K = 256, N = 1024
            gemm_mma_kernel<<<dim3(G4 / 128, W / 128), 256, GEMM_SMEM_BYTES>>>(
                Hdir, Whh, nullptr, XG + (size_t)t * W * G4, G, G4, HH);
            char_update_kernel<<<(W * HH) / 256, 256>>>(G, lens, Hdir, Cc, t);
        }
    }

    // ---- word-level input ----
    gather_word_kernel<<<W, 256>>>(wseq, wemb, Hf, Hb, WX);
    // XGw = WX @ WihT + bias:  M = 8192, K = 832, N = 1024
    gemm_mma_kernel<<<dim3(G4 / 128, W / 128), 256, GEMM_SMEM_BYTES>>>(
        WX, WihW + 0 * (size_t)G4 * WDINP, bias + 2 * G4, nullptr, XGw, G4, WDINP);
    gemm_mma_kernel<<<dim3(G4 / 128, W / 128), 256, GEMM_SMEM_BYTES>>>(
        WX, WihW + 1 * (size_t)G4 * WDINP, bias + 3 * G4, nullptr, XGw + (size_t)W * G4, G4, WDINP);

    // ---- sequential word BiLSTM: 32 flag-synced CTAs (16 per direction) ----
    zero_flags_kernel<<<4, 256>>>();
    word_lstm_kernel<<<2 * NCTA_DIR, 256>>>(XGw, wfWhh, wbWhh, OUT);

    // ---- heads + log_softmax ----
    heads_kernel<<<W, 128>>>(OUT, Wp, bp, Wp2, bp2, outp);

    (void)in_sizes; (void)n_in; (void)out_size;
}

// round 6
// speedup vs baseline: 1.3145x; 1.0287x over previous
#include <cuda_runtime.h>
#include <math.h>
#include <stdint.h>

// ---------------- problem constants ----------------
#define W     8192      // words
#define LC    16        // chars per word (padded)
#define CD    100       // char emb dim
#define CDP   128       // padded to %32 for tensor GEMM
#define WD    300       // word emb dim
#define HD    512       // hidden dim (bi)
#define HH    256       // per-direction hidden
#define G4    1024      // 4*HH gates
#define WDIN  812       // WD + HD
#define WDINP 832       // padded to %32
#define T1    48
#define T2    32

#define NCTA_DIR 16     // word-lstm CTAs per direction
#define CELLS    16     // cells per CTA

#define ALN __align__(16)

// smem layout constants for GEMM (floats)
#define KCH   32
#define RPAD  36
#define ABUF  (128 * RPAD)
#define BUFSZ (2 * ABUF)
#define GEMM_SMEM_BYTES (2 * BUFSZ * 4)   // 73728 B

// ---------------- static device scratch (no cudaMalloc allowed) ----------------
__device__ ALN float g_Xc[(size_t)LC * W * CDP];
__device__ ALN float g_XGf[(size_t)LC * W * G4];      // char input gates, fwd
__device__ ALN float g_XGb[(size_t)LC * W * G4];      // char input gates, bwd
__device__ ALN float g_Gc[2][(size_t)W * G4];         // per-step gate scratch (both dirs)
__device__ ALN float g_HC[4][(size_t)W * HH];         // Hf, Hb, Cf, Cb (contiguous for one zero)
__device__ ALN float g_WX[(size_t)W * WDINP];
__device__ ALN float g_XGw[(size_t)2 * W * G4];
__device__ ALN float g_OUT[(size_t)W * HD];
__device__ ALN float g_WihC[2][G4 * CDP];
__device__ ALN float g_WihW[2][G4 * WDINP];
__device__ ALN float g_bias[4][G4];
__device__ ALN unsigned long long g_hx[2][2][HH];     // [dir][parity][cell] = seq<<32 | h_bits

__device__ __forceinline__ float fast_sigmoid(float x) {
    return __fdividef(1.0f, 1.0f + __expf(-x));
}
__device__ __forceinline__ float fast_tanh(float x) {
    // 1 - 2/(e^{2x}+1); robust at +-inf via fdividef(x, inf) = 0
    return 1.0f - __fdividef(2.0f, __expf(2.0f * x) + 1.0f);
}

__device__ __forceinline__ uint32_t smem_u32(const void* p) {
    uint32_t a;
    asm("{ .reg .u64 t; cvta.to.shared.u64 t, %1; cvt.u32.u64 %0, t; }" : "=r"(a) : "l"(p));
    return a;
}
__device__ __forceinline__ uint32_t to_tf32(float x) {
    uint32_t u;
    asm("cvt.rna.tf32.f32 %0, %1;" : "=r"(u) : "f"(x));
    return u;
}
__device__ __forceinline__ unsigned long long ld_acq_u64(const unsigned long long* p) {
    unsigned long long v;
    asm volatile("ld.acquire.gpu.u64 %0, [%1];" : "=l"(v) : "l"(p) : "memory");
    return v;
}
__device__ __forceinline__ void st_rel_u64(unsigned long long* p, unsigned long long v) {
    asm volatile("st.release.gpu.u64 [%0], %1;" :: "l"(p), "l"(v) : "memory");
}
#define CP_ASYNC16(dst, src) \
    asm volatile("cp.async.cg.shared.global [%0], [%1], 16;" :: "r"(dst), "l"(src) : "memory")
#define CP_COMMIT()  asm volatile("cp.async.commit_group;" ::: "memory")
#define CP_WAIT(n)   asm volatile("cp.async.wait_group %0;" :: "n"(n) : "memory")

// ---------------- TF32 mma.sync dual GEMM ----------------
// z = blockIdx.z selects (A,B,bias,D,C) set. C[M,N] = A[M,K] @ B[N,K]^T (+bias) (+D).
__global__ __launch_bounds__(256, 2)
void gemm_mma_dual_kernel(const float* __restrict__ A0, const float* __restrict__ A1,
                          const float* __restrict__ B0, const float* __restrict__ B1,
                          const float* __restrict__ bias0, const float* __restrict__ bias1,
                          const float* __restrict__ D0, const float* __restrict__ D1,
                          float* __restrict__ C0, float* __restrict__ C1,
                          int N, int K)
{
    extern __shared__ ALN float smem[];

    const int tid = threadIdx.x;
    const int lane = tid & 31, wid = tid >> 5;
    const int wm = wid & 1, wn = wid >> 1;
    const int bx = blockIdx.x, by = blockIdx.y, bz = blockIdx.z;

    const float* A    = bz ? A1 : A0;
    const float* B    = bz ? B1 : B0;
    const float* bias = bz ? bias1 : bias0;
    const float* Dadd = bz ? D1 : D0;
    float*       C    = bz ? C1 : C0;

    const float* Abase = A + (size_t)(by * 128) * K;
    const float* Bbase = B + (size_t)(bx * 128) * K;

    float acc[4][4][4];
#pragma unroll
    for (int i = 0; i < 4; i++)
#pragma unroll
        for (int j = 0; j < 4; j++)
#pragma unroll
            for (int q = 0; q < 4; q++) acc[i][j][q] = 0.0f;

    const int nkt = K >> 5;

    {
        float* dst = smem;
#pragma unroll
        for (int i = 0; i < 4; i++) {
            int f = tid + i * 256;
            int row = f >> 3, c4 = f & 7;
            CP_ASYNC16(smem_u32(dst + row * RPAD + c4 * 4), Abase + (size_t)row * K + c4 * 4);
            CP_ASYNC16(smem_u32(dst + ABUF + row * RPAD + c4 * 4), Bbase + (size_t)row * K + c4 * 4);
        }
        CP_COMMIT();
    }

    for (int kt = 0; kt < nkt; kt++) {
        if (kt + 1 < nkt) {
            float* dst = smem + ((kt + 1) & 1) * BUFSZ;
            const float* Ak = Abase + (kt + 1) * KCH;
            const float* Bk = Bbase + (kt + 1) * KCH;
#pragma unroll
            for (int i = 0; i < 4; i++) {
                int f = tid + i * 256;
                int row = f >> 3, c4 = f & 7;
                CP_ASYNC16(smem_u32(dst + row * RPAD + c4 * 4), Ak + (size_t)row * K + c4 * 4);
                CP_ASYNC16(smem_u32(dst + ABUF + row * RPAD + c4 * 4), Bk + (size_t)row * K + c4 * 4);
            }
            CP_COMMIT();
            CP_WAIT(1);
        } else {
            CP_WAIT(0);
        }
        __syncthreads();

        const float* As = smem + (kt & 1) * BUFSZ;
        const float* Bs = As + ABUF;

#pragma unroll
        for (int kk = 0; kk < 4; kk++) {
            const int k0 = kk * 8 + (lane & 3);
            const int rA = wm * 64 + (lane >> 2);
            uint32_t a[4][4];
#pragma unroll
            for (int ms = 0; ms < 4; ms++) {
                const float* ap = As + (rA + ms * 16) * RPAD + k0;
                a[ms][0] = to_tf32(ap[0]);
                a[ms][1] = to_tf32(ap[8 * RPAD]);
                a[ms][2] = to_tf32(ap[4]);
                a[ms][3] = to_tf32(ap[8 * RPAD + 4]);
            }
            uint32_t b[4][2];
            const int nB = wn * 32 + (lane >> 2);
#pragma unroll
            for (int ns = 0; ns < 4; ns++) {
                const float* bp = Bs + (nB + ns * 8) * RPAD + k0;
                b[ns][0] = to_tf32(bp[0]);
                b[ns][1] = to_tf32(bp[4]);
            }
#pragma unroll
            for (int ms = 0; ms < 4; ms++)
#pragma unroll
                for (int ns = 0; ns < 4; ns++) {
                    asm volatile(
                        "mma.sync.aligned.m16n8k8.row.col.f32.tf32.tf32.f32 "
                        "{%0,%1,%2,%3}, {%4,%5,%6,%7}, {%8,%9}, {%0,%1,%2,%3};"
                        : "+f"(acc[ms][ns][0]), "+f"(acc[ms][ns][1]),
                          "+f"(acc[ms][ns][2]), "+f"(acc[ms][ns][3])
                        : "r"(a[ms][0]), "r"(a[ms][1]), "r"(a[ms][2]), "r"(a[ms][3]),
                          "r"(b[ns][0]), "r"(b[ns][1]));
                }
        }
        __syncthreads();
    }

#pragma unroll
    for (int ms = 0; ms < 4; ms++) {
        int row = by * 128 + wm * 64 + ms * 16 + (lane >> 2);
#pragma unroll
        for (int ns = 0; ns < 4; ns++) {
            int col = bx * 128 + wn * 32 + ns * 8 + (lane & 3) * 2;
            float2 bb = make_float2(0.f, 0.f);
            if (bias) bb = *(const float2*)(bias + col);
            {
                float2 v = make_float2(acc[ms][ns][0] + bb.x, acc[ms][ns][1] + bb.y);
                if (Dadd) {
                    float2 dd = *(const float2*)(Dadd + (size_t)row * N + col);
                    v.x += dd.x; v.y += dd.y;
                }
                *(float2*)(C + (size_t)row * N + col) = v;
            }
            {
                float2 v = make_float2(acc[ms][ns][2] + bb.x, acc[ms][ns][3] + bb.y);
                if (Dadd) {
                    float2 dd = *(const float2*)(Dadd + (size_t)(row + 8) * N + col);
                    v.x += dd.x; v.y += dd.y;
                }
                *(float2*)(C + (size_t)(row + 8) * N + col) = v;
            }
        }
    }
}

// ---------------- small utility kernels ----------------
__global__ void zero_kernel(float* p, size_t n) {
    size_t i = (size_t)blockIdx.x * blockDim.x + threadIdx.x;
    if (i < n) p[i] = 0.0f;
}

__global__ void zero_hx_kernel() {
    int i = blockIdx.x * blockDim.x + threadIdx.x;   // 2*2*256 = 1024 slots
    if (i < 2 * 2 * HH) ((unsigned long long*)g_hx)[i] = 0ull;
}

__global__ void pack_wihc_kernel(const float* __restrict__ src, float* __restrict__ dst) {
    int n = blockIdx.x;
    for (int k = threadIdx.x; k < CDP; k += blockDim.x)
        dst[n * CDP + k] = (k < CD) ? src[n * CD + k] : 0.0f;
}

__global__ void pack_wihw_kernel(const float* __restrict__ src, float* __restrict__ dst) {
    int n = blockIdx.x;
    for (int k = threadIdx.x; k < WDINP; k += blockDim.x)
        dst[n * WDINP + k] = (k < WDIN) ? src[n * WDIN + k] : 0.0f;
}

__global__ void bias_sum_kernel(const float* __restrict__ a, const float* __restrict__ b,
                                float* __restrict__ o) {
    int i = blockIdx.x * blockDim.x + threadIdx.x;
    if (i < G4) o[i] = a[i] + b[i];
}

__global__ void gather_char_kernel(const int* __restrict__ cseq, const float* __restrict__ cemb,
                                   float* __restrict__ Xc) {
    int id = blockIdx.x;            // id = t*W + w
    int t = id >> 13;
    int w = id & (W - 1);
    int ci = cseq[w * LC + t];
    float* dst = Xc + (size_t)id * CDP;
    const float* src = cemb + (size_t)ci * CD;
    for (int k = threadIdx.x; k < CDP; k += blockDim.x)
        dst[k] = (k < CD) ? src[k] : 0.0f;
}

__global__ void gather_word_kernel(const int* __restrict__ wseq, const float* __restrict__ wemb,
                                   const float* __restrict__ Hf, const float* __restrict__ Hb,
                                   float* __restrict__ WX) {
    int w = blockIdx.x;
    int wi = wseq[w];
    float* dst = WX + (size_t)w * WDINP;
    for (int k = threadIdx.x; k < WDINP; k += blockDim.x) {
        float v;
        if (k < WD)            v = wemb[(size_t)wi * WD + k];
        else if (k < WD + HH)  v = Hf[(size_t)w * HH + (k - WD)];
        else if (k < WDIN)     v = Hb[(size_t)w * HH + (k - WD - HH)];
        else                   v = 0.0f;
        dst[k] = v;
    }
}

// ---------------- char LSTM pointwise update, both directions ----------------
__global__ void char_update_dual_kernel(const float* __restrict__ lensf,  // unused pad
                                        const int* __restrict__ lens,
                                        float* __restrict__ Hf, float* __restrict__ Hb,
                                        float* __restrict__ Cf, float* __restrict__ Cb,
                                        int tf, int tb)
{
    int dir = blockIdx.y;
    int idx = blockIdx.x * blockDim.x + threadIdx.x;   // w*256 + j
    int w = idx >> 8;
    int j = idx & 255;
    int t = dir ? tb : tf;
    if (t >= lens[w]) return;
    const float* gr = g_Gc[dir] + (size_t)w * G4;
    float* Hs = dir ? Hb : Hf;
    float* Cs = dir ? Cb : Cf;
    float gi = gr[j], gf = gr[256 + j], gg = gr[512 + j], go = gr[768 + j];
    float c = Cs[idx];
    float cn = fast_sigmoid(gf) * c + fast_sigmoid(gi) * fast_tanh(gg);
    float hn = fast_sigmoid(go) * fast_tanh(cn);
    Hs[idx] = hn;
    Cs[idx] = cn;
    (void)lensf;
}

// ---------------- sequential word BiLSTM: dataflow-synced via packed (seq|h) words ---------
// grid = 32 CTAs: d = bid/16 (direction), b = bid%16 (cells [b*16, b*16+16)).
// 256 threads: tid = r*4 + q; r = local gate row (0..63), q = h-quarter (64 floats).
// Thread owns Whh[(r>>4)*256 + b*16 + (r&15)][q*64 .. +64) in registers.
// Each cell's h is published as ONE 8-byte release store: (seq+1)<<32 | h_bits, into a
// parity-double-buffered slot. Every thread polls exactly one cell with an acquire load;
// the poll IS the readback. No fences, no barrier-of-maxes: pure dataflow, 1-step skew cap.
__global__ __launch_bounds__(256, 1) void word_lstm_kernel(
    const float* __restrict__ XGw,
    const float* __restrict__ WhhF, const float* __restrict__ WhhB,
    float* __restrict__ OUT)
{
    const int d = blockIdx.x >> 4;
    const int b = blockIdx.x & 15;
    const int tid = threadIdx.x;
    const int r = tid >> 2;          // local row 0..63
    const int q = tid & 3;           // quarter
    const int rowg = ((r >> 4) << 8) + b * CELLS + (r & 15);

    const float* Whh = d ? WhhB : WhhF;
    const float* xgbase = XGw + (size_t)d * W * G4;

    __shared__ ALN float h_sh[HH];
    __shared__ ALN float gsh[64];

    float wreg[64];
#pragma unroll
    for (int i = 0; i < 64; i += 4) {
        float4 v = *(const float4*)(Whh + (size_t)rowg * HH + q * 64 + i);
        wreg[i] = v.x; wreg[i + 1] = v.y; wreg[i + 2] = v.z; wreg[i + 3] = v.w;
    }
    h_sh[tid] = 0.0f;
    float c = 0.0f;
    __syncthreads();

    // xg for this thread's row, prefetched one step ahead (only q==0 lanes use it)
    float xg_cur = 0.0f;
    if (q == 0) xg_cur = __ldg(xgbase + (size_t)(d ? (W - 1) : 0) * G4 + rowg);

    unsigned long long* slot_pub[2];
    slot_pub[0] = &g_hx[d][0][b * CELLS + (tid & 15)];
    slot_pub[1] = &g_hx[d][1][b * CELLS + (tid & 15)];
    unsigned long long* slot_sub[2] = { &g_hx[d][0][tid], &g_hx[d][1][tid] };

    for (int t = 0; t < W; t++) {
        const int p = d ? (W - 1 - t) : t;

        // prefetch next xg (hidden under this whole step)
        float xg_next = 0.0f;
        if (q == 0 && t + 1 < W) {
            int pn = d ? (W - 2 - t) : (t + 1);
            xg_next = __ldg(xgbase + (size_t)pn * G4 + rowg);
        }

        // matvec partial: 64 MACs from smem h
        const float* hb = &h_sh[q * 64];
        float s0 = 0.f, s1 = 0.f, s2 = 0.f, s3 = 0.f;
#pragma unroll
        for (int i = 0; i < 64; i += 4) {
            float4 h4 = *(const float4*)(hb + i);
            s0 = fmaf(h4.x, wreg[i],     s0);
            s1 = fmaf(h4.y, wreg[i + 1], s1);
            s2 = fmaf(h4.z, wreg[i + 2], s2);
            s3 = fmaf(h4.w, wreg[i + 3], s3);
        }
        float s = (s0 + s1) + (s2 + s3);
        // in-warp reduce over the 4 quarters (lanes differing in bits 0..1)
        s += __shfl_xor_sync(0xFFFFFFFFu, s, 1);
        s += __shfl_xor_sync(0xFFFFFFFFu, s, 2);
        if (q == 0) gsh[r] = xg_cur + s;
        __syncthreads();                 // gsh ready; also: everyone done reading h_sh

        if (tid < CELLS) {
            float gi = gsh[tid], gf = gsh[16 + tid], gg = gsh[32 + tid], go = gsh[48 + tid];
            float cn = fast_sigmoid(gf) * c + fast_sigmoid(gi) * fast_tanh(gg);
            c = cn;
            float hn = fast_sigmoid(go) * fast_tanh(cn);
            unsigned long long pv = ((unsigned long long)(unsigned)(t + 1) << 32)
                                  | (unsigned long long)__float_as_uint(hn);
            st_rel_u64(slot_pub[(t + 1) & 1], pv);
            OUT[(size_t)p * HD + d * HH + b * CELLS + tid] = hn;
        }

        // every thread polls its one cell for the next step's h
        {
            const unsigned target = (unsigned)(t + 1);
            unsigned long long* sl = slot_sub[(t + 1) & 1];
            unsigned long long v = ld_acq_u64(sl);
            while ((unsigned)(v >> 32) != target) v = ld_acq_u64(sl);
            h_sh[tid] = __uint_as_float((unsigned)v);
        }
        __syncthreads();

        xg_cur = xg_next;
    }
}

// ---------------- heads: logits + log_softmax ----------------
__global__ __launch_bounds__(128) void heads_kernel(
    const float* __restrict__ OUT,
    const float* __restrict__ Wp, const float* __restrict__ bp,
    const float* __restrict__ Wp2, const float* __restrict__ bp2,
    float* __restrict__ out)
{
    int w = blockIdx.x;
    __shared__ ALN float osh[HD];
    __shared__ ALN float lsh[T1 + T2];
    int tid = threadIdx.x;
    int lane = tid & 31, wid = tid >> 5;

    for (int k = tid; k < HD; k += 128) osh[k] = OUT[(size_t)w * HD + k];
    __syncthreads();

    for (int l = wid; l < T1 + T2; l += 4) {
        const float* wr = (l < T1) ? (Wp + (size_t)l * HD) : (Wp2 + (size_t)(l - T1) * HD);
        float s = 0.0f;
#pragma unroll 4
        for (int k = lane; k < HD; k += 32) s = fmaf(osh[k], wr[k], s);
#pragma unroll
        for (int o = 16; o; o >>= 1) s += __shfl_xor_sync(0xFFFFFFFFu, s, o);
        if (lane == 0) lsh[l] = s + ((l < T1) ? bp[l] : bp2[l - T1]);
    }
    __syncthreads();

    if (wid < 2) {
        int T = (wid == 0) ? T1 : T2;
        int base = (wid == 0) ? 0 : T1;
        float* ob = (wid == 0) ? (out + (size_t)w * T1)
                               : (out + (size_t)W * T1 + (size_t)w * T2);
        float mx = -1e30f;
        for (int l = lane; l < T; l += 32) mx = fmaxf(mx, lsh[base + l]);
#pragma unroll
        for (int o = 16; o; o >>= 1) mx = fmaxf(mx, __shfl_xor_sync(0xFFFFFFFFu, mx, o));
        float se = 0.0f;
        for (int l = lane; l < T; l += 32) se += expf(lsh[base + l] - mx);
#pragma unroll
        for (int o = 16; o; o >>= 1) se += __shfl_xor_sync(0xFFFFFFFFu, se, o);
        float lz = mx + logf(se);
        for (int l = lane; l < T; l += 32) ob[l] = lsh[base + l] - lz;
    }
}

// ---------------- host orchestration ----------------
static void* sym(const void* s) {
    void* p = nullptr;
    cudaGetSymbolAddress(&p, s);
    return p;
}

extern "C" void kernel_launch(void* const* d_in, const int* in_sizes, int n_in,
                              void* d_out, int out_size)
{
    const int*   wseq  = (const int*)d_in[0];
    const int*   cseq  = (const int*)d_in[1];
    const int*   lens  = (const int*)d_in[2];
    const float* cemb  = (const float*)d_in[3];
    const float* wemb  = (const float*)d_in[4];
    const float* cfWih = (const float*)d_in[5];
    const float* cfWhh = (const float*)d_in[6];
    const float* cfbih = (const float*)d_in[7];
    const float* cfbhh = (const float*)d_in[8];
    const float* cbWih = (const float*)d_in[9];
    const float* cbWhh = (const float*)d_in[10];
    const float* cbbih = (const float*)d_in[11];
    const float* cbbhh = (const float*)d_in[12];
    const float* wfWih = (const float*)d_in[13];
    const float* wfWhh = (const float*)d_in[14];
    const float* wfbih = (const float*)d_in[15];
    const float* wfbhh = (const float*)d_in[16];
    const float* wbWih = (const float*)d_in[17];
    const float* wbWhh = (const float*)d_in[18];
    const float* wbbih = (const float*)d_in[19];
    const float* wbbhh = (const float*)d_in[20];
    const float* Wp    = (const float*)d_in[21];
    const float* bp    = (const float*)d_in[22];
    const float* Wp2   = (const float*)d_in[23];
    const float* bp2   = (const float*)d_in[24];
    float* outp = (float*)d_out;

    float* Xc   = (float*)sym(g_Xc);
    float* XGf  = (float*)sym(g_XGf);
    float* XGb  = (float*)sym(g_XGb);
    float* Gc   = (float*)sym(g_Gc);
    float* HC   = (float*)sym(g_HC);
    float* WX   = (float*)sym(g_WX);
    float* XGw  = (float*)sym(g_XGw);
    float* OUT  = (float*)sym(g_OUT);
    float* WihC = (float*)sym(g_WihC);
    float* WihW = (float*)sym(g_WihW);
    float* bias = (float*)sym(g_bias);

    float* Hf = HC + 0 * (size_t)W * HH;
    float* Hb = HC + 1 * (size_t)W * HH;
    float* Cf = HC + 2 * (size_t)W * HH;
    float* Cb = HC + 3 * (size_t)W * HH;
    float* Gc0 = Gc;
    float* Gc1 = Gc + (size_t)W * G4;

    cudaFuncSetAttribute(gemm_mma_dual_kernel, cudaFuncAttributeMaxDynamicSharedMemorySize,
                         GEMM_SMEM_BYTES);

    // ---- pack weights / biases ----
    pack_wihc_kernel<<<G4, 128>>>(cfWih, WihC + 0 * (size_t)G4 * CDP);
    pack_wihc_kernel<<<G4, 128>>>(cbWih, WihC + 1 * (size_t)G4 * CDP);
    pack_wihw_kernel<<<G4, 256>>>(wfWih, WihW + 0 * (size_t)G4 * WDINP);
    pack_wihw_kernel<<<G4, 256>>>(wbWih, WihW + 1 * (size_t)G4 * WDINP);
    bias_sum_kernel<<<4, 256>>>(cfbih, cfbhh, bias + 0 * G4);
    bias_sum_kernel<<<4, 256>>>(cbbih, cbbhh, bias + 1 * G4);
    bias_sum_kernel<<<4, 256>>>(wfbih, wfbhh, bias + 2 * G4);
    bias_sum_kernel<<<4, 256>>>(wbbih, wbbhh, bias + 3 * G4);

    // ---- gather char embeddings ----
    gather_char_kernel<<<LC * W, 128>>>(cseq, cemb, Xc);

    // ---- char BiLSTM, both directions together ----
    const size_t nState = (size_t)4 * W * HH;
    zero_kernel<<<(unsigned)((nState + 255) / 256), 256>>>(HC, nState);

    // XG{f,b} = Xc @ Wih{f,b}^T + bias:  M = 131072, K = 128, N = 1024
    gemm_mma_dual_kernel<<<dim3(G4 / 128, (LC * W) / 128, 2), 256, GEMM_SMEM_BYTES>>>(
        Xc, Xc, WihC, WihC + (size_t)G4 * CDP, bias, bias + G4,
        nullptr, nullptr, XGf, XGb, G4, CDP);

    for (int s = 0; s < LC; s++) {
        int tf = s, tb = LC - 1 - s;
        // G{0,1} = H{f,b} @ Whh{f,b}^T + XG{f,b}[t]:  M = 8192, K = 256, N = 1024
        gemm_mma_dual_kernel<<<dim3(G4 / 128, W / 128, 2), 256, GEMM_SMEM_BYTES>>>(
            Hf, Hb, cfWhh, cbWhh, nullptr, nullptr,
            XGf + (size_t)tf * W * G4, XGb + (size_t)tb * W * G4,
            Gc0, Gc1, G4, HH);
        char_update_dual_kernel<<<dim3((W * HH) / 256, 2), 256>>>(
            nullptr, lens, Hf, Hb, Cf, Cb, tf, tb);
    }

    // ---- word-level input ----
    gather_word_kernel<<<W, 256>>>(wseq, wemb, Hf, Hb, WX);
    // XGw = WX @ WihW{f,b}^T + bias:  M = 8192, K = 832, N = 1024
    gemm_mma_dual_kernel<<<dim3(G4 / 128, W / 128, 2), 256, GEMM_SMEM_BYTES>>>(
        WX, WX, WihW, WihW + (size_t)G4 * WDINP, bias + 2 * G4, bias + 3 * G4,
        nullptr, nullptr, XGw, XGw + (size_t)W * G4, G4, WDINP);

    // ---- sequential word BiLSTM: 32 dataflow-synced CTAs ----
    zero_hx_kernel<<<4, 256>>>();
    word_lstm_kernel<<<2 * NCTA_DIR, 256>>>(XGw, wfWhh, wbWhh, OUT);

    // ---- heads + log_softmax ----
    heads_kernel<<<W, 128>>>(OUT, Wp, bp, Wp2, bp2, outp);

    (void)in_sizes; (void)n_in; (void)out_size;
}

// round 9
// speedup vs baseline: 1.3173x; 1.0021x over previous
#include <cuda_runtime.h>
#include <math.h>
#include <stdint.h>

// ---------------- problem constants ----------------
#define W     8192      // words
#define LC    16        // chars per word (padded)
#define CD    100       // char emb dim
#define CDP   128       // padded to %32 for tensor GEMM
#define WD    300       // word emb dim
#define HD    512       // hidden dim (bi)
#define HH    256       // per-direction hidden
#define G4    1024      // 4*HH gates
#define WDIN  812       // WD + HD
#define WDINP 832       // padded to %32
#define T1    48
#define T2    32

#define NCTA_DIR 16     // word-lstm CTAs per direction
#define CELLS    16     // cells per CTA

#define ALN __align__(16)

// smem layout constants for GEMM (floats)
#define KCH   32
#define RPAD  36
#define ABUF  (128 * RPAD)
#define BUFSZ (2 * ABUF)
#define GEMM_SMEM_BYTES (2 * BUFSZ * 4)   // 73728 B

// ---------------- static device scratch (no cudaMalloc allowed) ----------------
__device__ ALN float g_Xc[(size_t)LC * W * CDP];
__device__ ALN float g_XGf[(size_t)LC * W * G4];      // char input gates, fwd
__device__ ALN float g_XGb[(size_t)LC * W * G4];      // char input gates, bwd
__device__ ALN float g_Gc[2][(size_t)W * G4];         // per-step gate scratch (both dirs)
__device__ ALN float g_HC[4][(size_t)W * HH];         // Hf, Hb, Cf, Cb
__device__ ALN float g_WX[(size_t)W * WDINP];
__device__ ALN float g_XGw[(size_t)2 * W * G4];
__device__ ALN float g_OUT[(size_t)W * HD];
__device__ ALN float g_WihC[2][G4 * CDP];
__device__ ALN float g_WihW[2][G4 * WDINP];
__device__ ALN float g_bias[4][G4];
__device__ ALN unsigned long long g_hx[2][2][HH];     // [dir][parity][cell] = seq<<32 | h_bits

__device__ __forceinline__ float fast_sigmoid(float x) {
    return __fdividef(1.0f, 1.0f + __expf(-x));
}
__device__ __forceinline__ float fast_tanh(float x) {
    return 1.0f - __fdividef(2.0f, __expf(2.0f * x) + 1.0f);
}

__device__ __forceinline__ uint32_t smem_u32(const void* p) {
    uint32_t a;
    asm("{ .reg .u64 t; cvta.to.shared.u64 t, %1; cvt.u32.u64 %0, t; }" : "=r"(a) : "l"(p));
    return a;
}
__device__ __forceinline__ uint32_t to_tf32(float x) {
    uint32_t u;
    asm("cvt.rna.tf32.f32 %0, %1;" : "=r"(u) : "f"(x));
    return u;
}
__device__ __forceinline__ unsigned long long ld_acq_u64(const unsigned long long* p) {
    unsigned long long v;
    asm volatile("ld.acquire.gpu.u64 %0, [%1];" : "=l"(v) : "l"(p) : "memory");
    return v;
}
__device__ __forceinline__ void st_rel_u64(unsigned long long* p, unsigned long long v) {
    asm volatile("st.release.gpu.u64 [%0], %1;" :: "l"(p), "l"(v) : "memory");
}
#define CP_ASYNC16(dst, src) \
    asm volatile("cp.async.cg.shared.global [%0], [%1], 16;" :: "r"(dst), "l"(src) : "memory")
#define CP_COMMIT()  asm volatile("cp.async.commit_group;" ::: "memory")
#define CP_WAIT(n)   asm volatile("cp.async.wait_group %0;" :: "n"(n) : "memory")

// ---------------- TF32 mma.sync dual GEMM ----------------
__global__ __launch_bounds__(256, 2)
void gemm_mma_dual_kernel(const float* __restrict__ A0, const float* __restrict__ A1,
                          const float* __restrict__ B0, const float* __restrict__ B1,
                          const float* __restrict__ bias0, const float* __restrict__ bias1,
                          const float* __restrict__ D0, const float* __restrict__ D1,
                          float* __restrict__ C0, float* __restrict__ C1,
                          int N, int K)
{
    extern __shared__ ALN float smem[];

    const int tid = threadIdx.x;
    const int lane = tid & 31, wid = tid >> 5;
    const int wm = wid & 1, wn = wid >> 1;
    const int bx = blockIdx.x, by = blockIdx.y, bz = blockIdx.z;

    const float* A    = bz ? A1 : A0;
    const float* B    = bz ? B1 : B0;
    const float* bias = bz ? bias1 : bias0;
    const float* Dadd = bz ? D1 : D0;
    float*       C    = bz ? C1 : C0;

    const float* Abase = A + (size_t)(by * 128) * K;
    const float* Bbase = B + (size_t)(bx * 128) * K;

    float acc[4][4][4];
#pragma unroll
    for (int i = 0; i < 4; i++)
#pragma unroll
        for (int j = 0; j < 4; j++)
#pragma unroll
            for (int q = 0; q < 4; q++) acc[i][j][q] = 0.0f;

    const int nkt = K >> 5;

    {
        float* dst = smem;
#pragma unroll
        for (int i = 0; i < 4; i++) {
            int f = tid + i * 256;
            int row = f >> 3, c4 = f & 7;
            CP_ASYNC16(smem_u32(dst + row * RPAD + c4 * 4), Abase + (size_t)row * K + c4 * 4);
            CP_ASYNC16(smem_u32(dst + ABUF + row * RPAD + c4 * 4), Bbase + (size_t)row * K + c4 * 4);
        }
        CP_COMMIT();
    }

    for (int kt = 0; kt < nkt; kt++) {
        if (kt + 1 < nkt) {
            float* dst = smem + ((kt + 1) & 1) * BUFSZ;
            const float* Ak = Abase + (kt + 1) * KCH;
            const float* Bk = Bbase + (kt + 1) * KCH;
#pragma unroll
            for (int i = 0; i < 4; i++) {
                int f = tid + i * 256;
                int row = f >> 3, c4 = f & 7;
                CP_ASYNC16(smem_u32(dst + row * RPAD + c4 * 4), Ak + (size_t)row * K + c4 * 4);
                CP_ASYNC16(smem_u32(dst + ABUF + row * RPAD + c4 * 4), Bk + (size_t)row * K + c4 * 4);
            }
            CP_COMMIT();
            CP_WAIT(1);
        } else {
            CP_WAIT(0);
        }
        __syncthreads();

        const float* As = smem + (kt & 1) * BUFSZ;
        const float* Bs = As + ABUF;

#pragma unroll
        for (int kk = 0; kk < 4; kk++) {
            const int k0 = kk * 8 + (lane & 3);
            const int rA = wm * 64 + (lane >> 2);
            uint32_t a[4][4];
#pragma unroll
            for (int ms = 0; ms < 4; ms++) {
                const float* ap = As + (rA + ms * 16) * RPAD + k0;
                a[ms][0] = to_tf32(ap[0]);
                a[ms][1] = to_tf32(ap[8 * RPAD]);
                a[ms][2] = to_tf32(ap[4]);
                a[ms][3] = to_tf32(ap[8 * RPAD + 4]);
            }
            uint32_t b[4][2];
            const int nB = wn * 32 + (lane >> 2);
#pragma unroll
            for (int ns = 0; ns < 4; ns++) {
                const float* bp = Bs + (nB + ns * 8) * RPAD + k0;
                b[ns][0] = to_tf32(bp[0]);
                b[ns][1] = to_tf32(bp[4]);
            }
#pragma unroll
            for (int ms = 0; ms < 4; ms++)
#pragma unroll
                for (int ns = 0; ns < 4; ns++) {
                    asm volatile(
                        "mma.sync.aligned.m16n8k8.row.col.f32.tf32.tf32.f32 "
                        "{%0,%1,%2,%3}, {%4,%5,%6,%7}, {%8,%9}, {%0,%1,%2,%3};"
                        : "+f"(acc[ms][ns][0]), "+f"(acc[ms][ns][1]),
                          "+f"(acc[ms][ns][2]), "+f"(acc[ms][ns][3])
                        : "r"(a[ms][0]), "r"(a[ms][1]), "r"(a[ms][2]), "r"(a[ms][3]),
                          "r"(b[ns][0]), "r"(b[ns][1]));
                }
        }
        __syncthreads();
    }

#pragma unroll
    for (int ms = 0; ms < 4; ms++) {
        int row = by * 128 + wm * 64 + ms * 16 + (lane >> 2);
#pragma unroll
        for (int ns = 0; ns < 4; ns++) {
            int col = bx * 128 + wn * 32 + ns * 8 + (lane & 3) * 2;
            float2 bb = make_float2(0.f, 0.f);
            if (bias) bb = *(const float2*)(bias + col);
            {
                float2 v = make_float2(acc[ms][ns][0] + bb.x, acc[ms][ns][1] + bb.y);
                if (Dadd) {
                    float2 dd = *(const float2*)(Dadd + (size_t)row * N + col);
                    v.x += dd.x; v.y += dd.y;
                }
                *(float2*)(C + (size_t)row * N + col) = v;
            }
            {
                float2 v = make_float2(acc[ms][ns][2] + bb.x, acc[ms][ns][3] + bb.y);
                if (Dadd) {
                    float2 dd = *(const float2*)(Dadd + (size_t)(row + 8) * N + col);
                    v.x += dd.x; v.y += dd.y;
                }
                *(float2*)(C + (size_t)(row + 8) * N + col) = v;
            }
        }
    }
}

// ---------------- small utility kernels ----------------
__global__ void zero_kernel(float* p, size_t n) {
    size_t i = (size_t)blockIdx.x * blockDim.x + threadIdx.x;
    if (i < n) p[i] = 0.0f;
}

__global__ void zero_hx_kernel() {
    int i = blockIdx.x * blockDim.x + threadIdx.x;   // 2*2*256 = 1024 slots
    if (i < 2 * 2 * HH) ((unsigned long long*)g_hx)[i] = 0ull;
}

__global__ void pack_wihc_kernel(const float* __restrict__ src, float* __restrict__ dst) {
    int n = blockIdx.x;
    for (int k = threadIdx.x; k < CDP; k += blockDim.x)
        dst[n * CDP + k] = (k < CD) ? src[n * CD + k] : 0.0f;
}

__global__ void pack_wihw_kernel(const float* __restrict__ src, float* __restrict__ dst) {
    int n = blockIdx.x;
    for (int k = threadIdx.x; k < WDINP; k += blockDim.x)
        dst[n * WDINP + k] = (k < WDIN) ? src[n * WDIN + k] : 0.0f;
}

__global__ void bias_sum_kernel(const float* __restrict__ a, const float* __restrict__ b,
                                float* __restrict__ o) {
    int i = blockIdx.x * blockDim.x + threadIdx.x;
    if (i < G4) o[i] = a[i] + b[i];
}

__global__ void gather_char_kernel(const int* __restrict__ cseq, const float* __restrict__ cemb,
                                   float* __restrict__ Xc) {
    int id = blockIdx.x;            // id = t*W + w
    int t = id >> 13;
    int w = id & (W - 1);
    int ci = cseq[w * LC + t];
    float* dst = Xc + (size_t)id * CDP;
    const float* src = cemb + (size_t)ci * CD;
    for (int k = threadIdx.x; k < CDP; k += blockDim.x)
        dst[k] = (k < CD) ? src[k] : 0.0f;
}

__global__ void gather_word_kernel(const int* __restrict__ wseq, const float* __restrict__ wemb,
                                   const float* __restrict__ Hf, const float* __restrict__ Hb,
                                   float* __restrict__ WX) {
    int w = blockIdx.x;
    int wi = wseq[w];
    float* dst = WX + (size_t)w * WDINP;
    for (int k = threadIdx.x; k < WDINP; k += blockDim.x) {
        float v;
        if (k < WD)            v = wemb[(size_t)wi * WD + k];
        else if (k < WD + HH)  v = Hf[(size_t)w * HH + (k - WD)];
        else if (k < WDIN)     v = Hb[(size_t)w * HH + (k - WD - HH)];
        else                   v = 0.0f;
        dst[k] = v;
    }
}

// ---------------- char LSTM pointwise update, both directions ----------------
__global__ void char_update_dual_kernel(const int* __restrict__ lens,
                                        float* __restrict__ Hf, float* __restrict__ Hb,
                                        float* __restrict__ Cf, float* __restrict__ Cb,
                                        int tf, int tb)
{
    int dir = blockIdx.y;
    int idx = blockIdx.x * blockDim.x + threadIdx.x;   // w*256 + j
    int w = idx >> 8;
    int j = idx & 255;
    int t = dir ? tb : tf;
    if (t >= lens[w]) return;
    const float* gr = g_Gc[dir] + (size_t)w * G4;
    float* Hs = dir ? Hb : Hf;
    float* Cs = dir ? Cb : Cf;
    float gi = gr[j], gf = gr[256 + j], gg = gr[512 + j], go = gr[768 + j];
    float c = Cs[idx];
    float cn = fast_sigmoid(gf) * c + fast_sigmoid(gi) * fast_tanh(gg);
    float hn = fast_sigmoid(go) * fast_tanh(cn);
    Hs[idx] = hn;
    Cs[idx] = cn;
}

// ---------------- sequential word BiLSTM: dataflow-synced, with poll backoff ----------------
// Identical to the round-6 PASS except the poll loop: 4 fast-path re-polls (zero added
// latency when in sync), then nanosleep(32) between acquire loads. Theory: 8192 threads
// spinning strong loads at issue rate congest the LTS and queue the critical-path release
// stores behind thousands of poll transactions; backoff cuts poll traffic ~30x.
__global__ __launch_bounds__(256, 1) void word_lstm_kernel(
    const float* __restrict__ XGw,
    const float* __restrict__ WhhF, const float* __restrict__ WhhB,
    float* __restrict__ OUT)
{
    const int d = blockIdx.x >> 4;
    const int b = blockIdx.x & 15;
    const int tid = threadIdx.x;
    const int r = tid >> 2;          // local row 0..63
    const int q = tid & 3;           // quarter
    const int rowg = ((r >> 4) << 8) + b * CELLS + (r & 15);

    const float* Whh = d ? WhhB : WhhF;
    const float* xgbase = XGw + (size_t)d * W * G4;

    __shared__ ALN float h_sh[HH];
    __shared__ ALN float gsh[64];

    float wreg[64];
#pragma unroll
    for (int i = 0; i < 64; i += 4) {
        float4 v = *(const float4*)(Whh + (size_t)rowg * HH + q * 64 + i);
        wreg[i] = v.x; wreg[i + 1] = v.y; wreg[i + 2] = v.z; wreg[i + 3] = v.w;
    }
    h_sh[tid] = 0.0f;
    float c = 0.0f;
    __syncthreads();

    float xg_cur = 0.0f;
    if (q == 0) xg_cur = __ldg(xgbase + (size_t)(d ? (W - 1) : 0) * G4 + rowg);

    unsigned long long* slot_pub[2];
    slot_pub[0] = &g_hx[d][0][b * CELLS + (tid & 15)];
    slot_pub[1] = &g_hx[d][1][b * CELLS + (tid & 15)];
    unsigned long long* slot_sub[2] = { &g_hx[d][0][tid], &g_hx[d][1][tid] };

    for (int t = 0; t < W; t++) {
        const int p = d ? (W - 1 - t) : t;

        float xg_next = 0.0f;
        if (q == 0 && t + 1 < W) {
            int pn = d ? (W - 2 - t) : (t + 1);
            xg_next = __ldg(xgbase + (size_t)pn * G4 + rowg);
        }

        const float* hb = &h_sh[q * 64];
        float s0 = 0.f, s1 = 0.f, s2 = 0.f, s3 = 0.f;
#pragma unroll
        for (int i = 0; i < 64; i += 4) {
            float4 h4 = *(const float4*)(hb + i);
            s0 = fmaf(h4.x, wreg[i],     s0);
            s1 = fmaf(h4.y, wreg[i + 1], s1);
            s2 = fmaf(h4.z, wreg[i + 2], s2);
            s3 = fmaf(h4.w, wreg[i + 3], s3);
        }
        float s = (s0 + s1) + (s2 + s3);
        s += __shfl_xor_sync(0xFFFFFFFFu, s, 1);
        s += __shfl_xor_sync(0xFFFFFFFFu, s, 2);
        if (q == 0) gsh[r] = xg_cur + s;
        __syncthreads();

        if (tid < CELLS) {
            float gi = gsh[tid], gf = gsh[16 + tid], gg = gsh[32 + tid], go = gsh[48 + tid];
            float cn = fast_sigmoid(gf) * c + fast_sigmoid(gi) * fast_tanh(gg);
            c = cn;
            float hn = fast_sigmoid(go) * fast_tanh(cn);
            unsigned long long pv = ((unsigned long long)(unsigned)(t + 1) << 32)
                                  | (unsigned long long)__float_as_uint(hn);
            st_rel_u64(slot_pub[(t + 1) & 1], pv);
            OUT[(size_t)p * HD + d * HH + b * CELLS + tid] = hn;
        }

        // poll own cell: bounded fast-path, then nanosleep backoff to keep the LTS clear
        {
            const unsigned target = (unsigned)(t + 1);
            unsigned long long* sl = slot_sub[(t + 1) & 1];
            unsigned long long v = ld_acq_u64(sl);
#pragma unroll
            for (int fp = 0; fp < 4 && (unsigned)(v >> 32) != target; fp++)
                v = ld_acq_u64(sl);
            while ((unsigned)(v >> 32) != target) {
                __nanosleep(32);
                v = ld_acq_u64(sl);
            }
            h_sh[tid] = __uint_as_float((unsigned)v);
        }
        __syncthreads();

        xg_cur = xg_next;
    }
}

// ---------------- heads: logits + log_softmax ----------------
__global__ __launch_bounds__(128) void heads_kernel(
    const float* __restrict__ OUT,
    const float* __restrict__ Wp, const float* __restrict__ bp,
    const float* __restrict__ Wp2, const float* __restrict__ bp2,
    float* __restrict__ out)
{
    int w = blockIdx.x;
    __shared__ ALN float osh[HD];
    __shared__ ALN float lsh[T1 + T2];
    int tid = threadIdx.x;
    int lane = tid & 31, wid = tid >> 5;

    for (int k = tid; k < HD; k += 128) osh[k] = OUT[(size_t)w * HD + k];
    __syncthreads();

    for (int l = wid; l < T1 + T2; l += 4) {
        const float* wr = (l < T1) ? (Wp + (size_t)l * HD) : (Wp2 + (size_t)(l - T1) * HD);
        float s = 0.0f;
#pragma unroll 4
        for (int k = lane; k < HD; k += 32) s = fmaf(osh[k], wr[k], s);
#pragma unroll
        for (int o = 16; o; o >>= 1) s += __shfl_xor_sync(0xFFFFFFFFu, s, o);
        if (lane == 0) lsh[l] = s + ((l < T1) ? bp[l] : bp2[l - T1]);
    }
    __syncthreads();

    if (wid < 2) {
        int T = (wid == 0) ? T1 : T2;
        int base = (wid == 0) ? 0 : T1;
        float* ob = (wid == 0) ? (out + (size_t)w * T1)
                               : (out + (size_t)W * T1 + (size_t)w * T2);
        float mx = -1e30f;
        for (int l = lane; l < T; l += 32) mx = fmaxf(mx, lsh[base + l]);
#pragma unroll
        for (int o = 16; o; o >>= 1) mx = fmaxf(mx, __shfl_xor_sync(0xFFFFFFFFu, mx, o));
        float se = 0.0f;
        for (int l = lane; l < T; l += 32) se += expf(lsh[base + l] - mx);
#pragma unroll
        for (int o = 16; o; o >>= 1) se += __shfl_xor_sync(0xFFFFFFFFu, se, o);
        float lz = mx + logf(se);
        for (int l = lane; l < T; l += 32) ob[l] = lsh[base + l] - lz;
    }
}

// ---------------- host orchestration ----------------
static void* sym(const void* s) {
    void* p = nullptr;
    cudaGetSymbolAddress(&p, s);
    return p;
}

extern "C" void kernel_launch(void* const* d_in, const int* in_sizes, int n_in,
                              void* d_out, int out_size)
{
    const int*   wseq  = (const int*)d_in[0];
    const int*   cseq  = (const int*)d_in[1];
    const int*   lens  = (const int*)d_in[2];
    const float* cemb  = (const float*)d_in[3];
    const float* wemb  = (const float*)d_in[4];
    const float* cfWih = (const float*)d_in[5];
    const float* cfWhh = (const float*)d_in[6];
    const float* cfbih = (const float*)d_in[7];
    const float* cfbhh = (const float*)d_in[8];
    const float* cbWih = (const float*)d_in[9];
    const float* cbWhh = (const float*)d_in[10];
    const float* cbbih = (const float*)d_in[11];
    const float* cbbhh = (const float*)d_in[12];
    const float* wfWih = (const float*)d_in[13];
    const float* wfWhh = (const float*)d_in[14];
    const float* wfbih = (const float*)d_in[15];
    const float* wfbhh = (const float*)d_in[16];
    const float* wbWih = (const float*)d_in[17];
    const float* wbWhh = (const float*)d_in[18];
    const float* wbbih = (const float*)d_in[19];
    const float* wbbhh = (const float*)d_in[20];
    const float* Wp    = (const float*)d_in[21];
    const float* bp    = (const float*)d_in[22];
    const float* Wp2   = (const float*)d_in[23];
    const float* bp2   = (const float*)d_in[24];
    float* outp = (float*)d_out;

    float* Xc   = (float*)sym(g_Xc);
    float* XGf  = (float*)sym(g_XGf);
    float* XGb  = (float*)sym(g_XGb);
    float* Gc   = (float*)sym(g_Gc);
    float* HC   = (float*)sym(g_HC);
    float* WX   = (float*)sym(g_WX);
    float* XGw  = (float*)sym(g_XGw);
    float* OUT  = (float*)sym(g_OUT);
    float* WihC = (float*)sym(g_WihC);
    float* WihW = (float*)sym(g_WihW);
    float* bias = (float*)sym(g_bias);

    float* Hf = HC + 0 * (size_t)W * HH;
    float* Hb = HC + 1 * (size_t)W * HH;
    float* Cf = HC + 2 * (size_t)W * HH;
    float* Cb = HC + 3 * (size_t)W * HH;
    float* Gc0 = Gc;
    float* Gc1 = Gc + (size_t)W * G4;

    cudaFuncSetAttribute(gemm_mma_dual_kernel, cudaFuncAttributeMaxDynamicSharedMemorySize,
                         GEMM_SMEM_BYTES);

    // ---- pack weights / biases ----
    pack_wihc_kernel<<<G4, 128>>>(cfWih, WihC + 0 * (size_t)G4 * CDP);
    pack_wihc_kernel<<<G4, 128>>>(cbWih, WihC + 1 * (size_t)G4 * CDP);
    pack_wihw_kernel<<<G4, 256>>>(wfWih, WihW + 0 * (size_t)G4 * WDINP);
    pack_wihw_kernel<<<G4, 256>>>(wbWih, WihW + 1 * (size_t)G4 * WDINP);
    bias_sum_kernel<<<4, 256>>>(cfbih, cfbhh, bias + 0 * G4);
    bias_sum_kernel<<<4, 256>>>(cbbih, cbbhh, bias + 1 * G4);
    bias_sum_kernel<<<4, 256>>>(wfbih, wfbhh, bias + 2 * G4);
    bias_sum_kernel<<<4, 256>>>(wbbih, wbbhh, bias + 3 * G4);

    // ---- gather char embeddings ----
    gather_char_kernel<<<LC * W, 128>>>(cseq, cemb, Xc);

    // ---- char BiLSTM, both directions together ----
    const size_t nState = (size_t)4 * W * HH;
    zero_kernel<<<(unsigned)((nState + 255) / 256), 256>>>(HC, nState);

    gemm_mma_dual_kernel<<<dim3(G4 / 128, (LC * W) / 128, 2), 256, GEMM_SMEM_BYTES>>>(
        Xc, Xc, WihC, WihC + (size_t)G4 * CDP, bias, bias + G4,
        nullptr, nullptr, XGf, XGb, G4, CDP);

    for (int s = 0; s < LC; s++) {
        int tf = s, tb = LC - 1 - s;
        gemm_mma_dual_kernel<<<dim3(G4 / 128, W / 128, 2), 256, GEMM_SMEM_BYTES>>>(
            Hf, Hb, cfWhh, cbWhh, nullptr, nullptr,
            XGf + (size_t)tf * W * G4, XGb + (size_t)tb * W * G4,
            Gc0, Gc1, G4, HH);
        char_update_dual_kernel<<<dim3((W * HH) / 256, 2), 256>>>(
            lens, Hf, Hb, Cf, Cb, tf, tb);
    }

    // ---- word-level input ----
    gather_word_kernel<<<W, 256>>>(wseq, wemb, Hf, Hb, WX);
    gemm_mma_dual_kernel<<<dim3(G4 / 128, W / 128, 2), 256, GEMM_SMEM_BYTES>>>(
        WX, WX, WihW, WihW + (size_t)G4 * WDINP, bias + 2 * G4, bias + 3 * G4,
        nullptr, nullptr, XGw, XGw + (size_t)W * G4, G4, WDINP);

    // ---- sequential word BiLSTM: 32 dataflow-synced CTAs ----
    zero_hx_kernel<<<4, 256>>>();
    word_lstm_kernel<<<2 * NCTA_DIR, 256>>>(XGw, wfWhh, wbWhh, OUT);

    // ---- heads + log_softmax ----
    heads_kernel<<<W, 128>>>(OUT, Wp, bp, Wp2, bp2, outp);

    (void)in_sizes; (void)n_in; (void)out_size;
}